// round 2
// baseline (speedup 1.0000x reference)
#include <cuda_runtime.h>
#include <cstdint>

#define N_NODES 100000
#define D 128
#define E_EDGES 640000

#define BM 64          // nodes per block in MLP
#define TM 8
#define TN 4
#define MLP_THREADS 256
#define N_PAD 100032   // 1563 * 64

// Scratch: h = x + aggregated   (tail rows stay zero; never stored to out)
__device__ float g_H[(size_t)N_PAD * D];

// ---------------------------------------------------------------------------
// Kernel 1: H = x  (also re-initializes the accumulator every graph replay)
// ---------------------------------------------------------------------------
__global__ void init_kernel(const float* __restrict__ x) {
    int i = blockIdx.x * blockDim.x + threadIdx.x;
    const int n4 = N_NODES * D / 4;
    if (i < n4) {
        ((float4*)g_H)[i] = ((const float4*)x)[i];
    }
}

// ---------------------------------------------------------------------------
// Kernel 2: scatter-add. One warp per edge; lane handles a float4 (4 dims).
// float4 atomicAdd (sm_90+) -> RED.E.ADD.F32.128 : 4x fewer L2 atomic ops.
// edge_index is int32 (JAX x64 disabled downcasts the "int64" to int32).
// ---------------------------------------------------------------------------
__global__ void scatter_kernel(const float* __restrict__ x,
                               const int* __restrict__ edge_index) {
    int gwarp = (blockIdx.x * blockDim.x + threadIdx.x) >> 5;
    int lane  = threadIdx.x & 31;
    if (gwarp >= E_EDGES) return;
    int r = edge_index[gwarp];            // source node
    int c = edge_index[E_EDGES + gwarp];  // destination node
    const float4* xs = (const float4*)(x + (size_t)r * D);
    float4*       hd = (float4*)(g_H + (size_t)c * D);
    float4 v = xs[lane];
    atomicAdd(&hd[lane], v);
}

// ---------------------------------------------------------------------------
// Kernel 3: fused MLP  out = relu(H@W1 + b1) @ W2 + b2
// Block: 256 threads, 64 nodes. W1, W2, H-tile, H1-tile all staged in smem.
// Thread tile 8(m) x 4(n). HS reads are warp-broadcast; W reads are LDS.128.
// ---------------------------------------------------------------------------
__global__ void __launch_bounds__(MLP_THREADS, 1)
mlp_kernel(const float* __restrict__ W1, const float* __restrict__ b1,
           const float* __restrict__ W2, const float* __restrict__ b2,
           float* __restrict__ out) {
    extern __shared__ float smem[];
    float* W1s = smem;               // 128*128
    float* W2s = W1s + D * D;        // 128*128
    float* HS  = W2s + D * D;        // 64*128
    float* H1s = HS  + BM * D;       // 64*128

    const int tid = threadIdx.x;

    // Stage weights (coalesced float4)
    {
        const float4* w1g = (const float4*)W1;
        const float4* w2g = (const float4*)W2;
        float4* w1s = (float4*)W1s;
        float4* w2s = (float4*)W2s;
        for (int i = tid; i < D * D / 4; i += MLP_THREADS) {
            w1s[i] = w1g[i];
            w2s[i] = w2g[i];
        }
    }
    // Stage H tile
    const int m0 = blockIdx.x * BM;
    {
        const float4* hg = (const float4*)(g_H + (size_t)m0 * D);
        float4* hs = (float4*)HS;
        for (int i = tid; i < BM * D / 4; i += MLP_THREADS) hs[i] = hg[i];
    }
    __syncthreads();

    const int tx = tid & 31;   // n group: covers 32*4 = 128 outputs
    const int ty = tid >> 5;   // m group: covers 8*8  = 64 rows
    const int n0 = tx * TN;
    const int mrow = ty * TM;

    float acc[TM][TN];

    // ---- GEMM1: H1 = relu(HS @ W1 + b1) ----
    {
        float bb[TN];
        #pragma unroll
        for (int j = 0; j < TN; j++) bb[j] = b1[n0 + j];
        #pragma unroll
        for (int i = 0; i < TM; i++)
            #pragma unroll
            for (int j = 0; j < TN; j++) acc[i][j] = bb[j];

        #pragma unroll 4
        for (int k = 0; k < D; k++) {
            float4 w = ((const float4*)(W1s + k * D))[tx];
            #pragma unroll
            for (int i = 0; i < TM; i++) {
                float h = HS[(mrow + i) * D + k];   // warp-broadcast
                acc[i][0] += h * w.x;
                acc[i][1] += h * w.y;
                acc[i][2] += h * w.z;
                acc[i][3] += h * w.w;
            }
        }
        #pragma unroll
        for (int i = 0; i < TM; i++) {
            float4 r;
            r.x = fmaxf(acc[i][0], 0.0f);
            r.y = fmaxf(acc[i][1], 0.0f);
            r.z = fmaxf(acc[i][2], 0.0f);
            r.w = fmaxf(acc[i][3], 0.0f);
            ((float4*)(H1s + (mrow + i) * D))[tx] = r;
        }
    }
    __syncthreads();

    // ---- GEMM2: out = H1 @ W2 + b2 ----
    {
        float bb[TN];
        #pragma unroll
        for (int j = 0; j < TN; j++) bb[j] = b2[n0 + j];
        #pragma unroll
        for (int i = 0; i < TM; i++)
            #pragma unroll
            for (int j = 0; j < TN; j++) acc[i][j] = bb[j];

        #pragma unroll 4
        for (int k = 0; k < D; k++) {
            float4 w = ((const float4*)(W2s + k * D))[tx];
            #pragma unroll
            for (int i = 0; i < TM; i++) {
                float h = H1s[(mrow + i) * D + k];  // warp-broadcast
                acc[i][0] += h * w.x;
                acc[i][1] += h * w.y;
                acc[i][2] += h * w.z;
                acc[i][3] += h * w.w;
            }
        }
        #pragma unroll
        for (int i = 0; i < TM; i++) {
            int m = m0 + mrow + i;
            if (m < N_NODES) {
                float4 r = make_float4(acc[i][0], acc[i][1], acc[i][2], acc[i][3]);
                ((float4*)(out + (size_t)m * D))[tx] = r;
            }
        }
    }
}

// ---------------------------------------------------------------------------
extern "C" void kernel_launch(void* const* d_in, const int* in_sizes, int n_in,
                              void* d_out, int out_size) {
    const float* x  = (const float*)d_in[0];
    const int*   ei = (const int*)d_in[1];
    const float* W1 = (const float*)d_in[2];
    const float* b1 = (const float*)d_in[3];
    const float* W2 = (const float*)d_in[4];
    const float* b2 = (const float*)d_in[5];
    float*       out = (float*)d_out;

    // 1) H = x
    {
        int n4 = N_NODES * D / 4;
        int threads = 256;
        int blocks = (n4 + threads - 1) / threads;
        init_kernel<<<blocks, threads>>>(x);
    }
    // 2) scatter-add: one warp per edge
    {
        int threads = 256;                       // 8 warps/block
        int blocks = (E_EDGES + 7) / 8;
        scatter_kernel<<<blocks, threads>>>(x, ei);
    }
    // 3) fused MLP
    {
        const int smem_bytes = (D * D * 2 + BM * D * 2) * (int)sizeof(float); // 196608
        cudaFuncSetAttribute(mlp_kernel,
                             cudaFuncAttributeMaxDynamicSharedMemorySize,
                             smem_bytes);
        int blocks = N_PAD / BM;                 // 1563
        mlp_kernel<<<blocks, MLP_THREADS, smem_bytes>>>(W1, b1, W2, b2, out);
    }
}

// round 4
// speedup vs baseline: 1.4175x; 1.4175x over previous
#include <cuda_runtime.h>
#include <cuda_bf16.h>
#include <cstdint>

#define N_NODES 100000
#define D 128
#define E_EDGES 640000

#define MTILE 128
#define NBLK 782                 // 782 * 128 = 100096
#define N_PAD 100096

__device__ float g_H[(size_t)N_PAD * D];

// ---------------------------------------------------------------------------
// Kernel 1: H = x
// ---------------------------------------------------------------------------
__global__ void init_kernel(const float* __restrict__ x) {
    int i = blockIdx.x * blockDim.x + threadIdx.x;
    const int n4 = N_NODES * D / 4;
    if (i < n4) ((float4*)g_H)[i] = ((const float4*)x)[i];
}

// ---------------------------------------------------------------------------
// Kernel 2: scatter-add, one warp per edge, float4 atomics (RED.128).
// ---------------------------------------------------------------------------
__global__ void scatter_kernel(const float* __restrict__ x,
                               const int* __restrict__ edge_index) {
    int gwarp = (blockIdx.x * blockDim.x + threadIdx.x) >> 5;
    int lane  = threadIdx.x & 31;
    if (gwarp >= E_EDGES) return;
    int r = edge_index[gwarp];
    int c = edge_index[E_EDGES + gwarp];
    const float4* xs = (const float4*)(x + (size_t)r * D);
    float4*       hd = (float4*)(g_H + (size_t)c * D);
    float4 v = xs[lane];
    atomicAdd(&hd[lane], v);
}

// ---------------------------------------------------------------------------
// Kernel 3: fused MLP on legacy tensor cores (mma.sync bf16, split-fp32 emu).
// 256 threads = 8 warps; warp tile 32(m) x 64(n); CTA tile 128x128.
// D = a_hi@w_hi + a_hi@w_lo + a_lo@w_hi  (a_lo@w_lo dropped, ~2^-18 rel).
// SMEM rows padded to 272B -> ldmatrix 8-row groups are bank-conflict-free.
// ---------------------------------------------------------------------------
#define RB 272                      // row stride bytes (136 bf16)
#define T_BYTES (128 * RB)          // 34816 per tile
#define SM_AHI 0
#define SM_ALO (T_BYTES)
#define SM_W1H (2 * T_BYTES)
#define SM_W1L (3 * T_BYTES)
#define SM_W2H (4 * T_BYTES)
#define SM_W2L (5 * T_BYTES)
#define SM_B1  (6 * T_BYTES)
#define SM_B2  (6 * T_BYTES + 512)
#define SM_TOTAL (6 * T_BYTES + 1024)   // 209920

__device__ __forceinline__ uint32_t smem_u32(const void* p) {
    uint32_t a;
    asm("{ .reg .u64 t; cvta.to.shared.u64 t, %1; cvt.u32.u64 %0, t; }"
        : "=r"(a) : "l"(p));
    return a;
}

#define LDSM_X4(r0, r1, r2, r3, addr) \
    asm volatile("ldmatrix.sync.aligned.m8n8.x4.shared.b16 {%0,%1,%2,%3}, [%4];" \
        : "=r"(r0), "=r"(r1), "=r"(r2), "=r"(r3) : "r"(addr))

__device__ __forceinline__ void mma_bf16(float* d, const uint32_t* a, const uint32_t* b) {
    asm volatile(
        "mma.sync.aligned.m16n8k16.row.col.f32.bf16.bf16.f32 "
        "{%0,%1,%2,%3}, {%4,%5,%6,%7}, {%8,%9}, {%0,%1,%2,%3};"
        : "+f"(d[0]), "+f"(d[1]), "+f"(d[2]), "+f"(d[3])
        : "r"(a[0]), "r"(a[1]), "r"(a[2]), "r"(a[3]), "r"(b[0]), "r"(b[1]));
}

__device__ __forceinline__ uint32_t pack_hi2(float a, float b) {
    __nv_bfloat162 p(__float2bfloat16(a), __float2bfloat16(b));
    return *(uint32_t*)&p;
}
__device__ __forceinline__ uint32_t pack_lo2(float a, float b) {
    float ra = a - __bfloat162float(__float2bfloat16(a));
    float rb = b - __bfloat162float(__float2bfloat16(b));
    __nv_bfloat162 p(__float2bfloat16(ra), __float2bfloat16(rb));
    return *(uint32_t*)&p;
}

// One warp GEMM pass: acc += Ahi@Whi + Ahi@Wlo + Alo@Whi over K=128.
__device__ __forceinline__ void warp_gemm(
    uint32_t sb, uint32_t a_hi, uint32_t a_lo, uint32_t w_hi, uint32_t w_lo,
    int m0, int n0, int lane, float acc[2][8][4])
{
    const int li = lane & 7;
    const int sub = lane >> 3;
    // A frag addressing: matrices (m0..7,k0..7),(m8..15,k0..7),(m0..7,k8..15),(m8..15,k8..15)
    const uint32_t a_off = (uint32_t)((li + (sub & 1) * 8) * RB + (sub >> 1) * 16);
    // B frag addressing ([n][k] storage): (n0..7,k0..7),(n0..7,k8..15),(n8..15,k0..7),(n8..15,k8..15)
    const uint32_t b_off = (uint32_t)((li + (sub >> 1) * 8) * RB + (sub & 1) * 16);

    #pragma unroll
    for (int ks = 0; ks < 8; ks++) {
        const uint32_t kchunk = (uint32_t)(ks * 32);   // 2 chunks * 16B per k-step
        uint32_t ah[2][4], al[2][4];
        #pragma unroll
        for (int mi = 0; mi < 2; mi++) {
            uint32_t base = (uint32_t)((m0 + mi * 16) * RB) + a_off + kchunk;
            LDSM_X4(ah[mi][0], ah[mi][1], ah[mi][2], ah[mi][3], sb + a_hi + base);
            LDSM_X4(al[mi][0], al[mi][1], al[mi][2], al[mi][3], sb + a_lo + base);
        }
        uint32_t bh[8][2], bl[8][2];
        #pragma unroll
        for (int nj = 0; nj < 4; nj++) {
            uint32_t base = (uint32_t)((n0 + nj * 16) * RB) + b_off + kchunk;
            uint32_t r0, r1, r2, r3;
            LDSM_X4(r0, r1, r2, r3, sb + w_hi + base);
            bh[nj * 2][0] = r0; bh[nj * 2][1] = r1;
            bh[nj * 2 + 1][0] = r2; bh[nj * 2 + 1][1] = r3;
            LDSM_X4(r0, r1, r2, r3, sb + w_lo + base);
            bl[nj * 2][0] = r0; bl[nj * 2][1] = r1;
            bl[nj * 2 + 1][0] = r2; bl[nj * 2 + 1][1] = r3;
        }
        #pragma unroll
        for (int mi = 0; mi < 2; mi++)
            #pragma unroll
            for (int ni = 0; ni < 8; ni++) {
                mma_bf16(acc[mi][ni], ah[mi], bh[ni]);
                mma_bf16(acc[mi][ni], ah[mi], bl[ni]);
                mma_bf16(acc[mi][ni], al[mi], bh[ni]);
            }
    }
}

__global__ void __launch_bounds__(256, 1)
mlp_mma_kernel(const float* __restrict__ W1, const float* __restrict__ b1,
               const float* __restrict__ W2, const float* __restrict__ b2,
               float* __restrict__ out) {
    extern __shared__ char smem[];
    const uint32_t sb = smem_u32(smem);
    const int tid = threadIdx.x;
    const int lane = tid & 31;
    const int wid = tid >> 5;
    const int wm = wid & 3;        // 4 m-tiles of 32
    const int wn = wid >> 2;       // 2 n-tiles of 64
    const int m0 = wm * 32;
    const int n0 = wn * 64;

    // ---- stage biases ----
    if (tid < 128) {
        ((float*)(smem + SM_B1))[tid] = b1[tid];
        ((float*)(smem + SM_B2))[tid] = b2[tid];
    }

    // ---- convert W1/W2 to split-bf16, [n][k] layout (transpose) ----
    for (int idx = tid; idx < D * D; idx += 256) {
        int k = idx >> 7, n = idx & 127;
        uint32_t so = (uint32_t)(n * RB + (k >> 3) * 16 + (k & 7) * 2);
        float v1 = W1[idx];
        __nv_bfloat16 h1 = __float2bfloat16(v1);
        *(__nv_bfloat16*)(smem + SM_W1H + so) = h1;
        *(__nv_bfloat16*)(smem + SM_W1L + so) =
            __float2bfloat16(v1 - __bfloat162float(h1));
        float v2 = W2[idx];
        __nv_bfloat16 h2 = __float2bfloat16(v2);
        *(__nv_bfloat16*)(smem + SM_W2H + so) = h2;
        *(__nv_bfloat16*)(smem + SM_W2L + so) =
            __float2bfloat16(v2 - __bfloat162float(h2));
    }

    // ---- load + split A = H tile (coalesced float4 reads) ----
    {
        const float4* hg = (const float4*)(g_H + (size_t)blockIdx.x * MTILE * D);
        for (int idx = tid; idx < 128 * 32; idx += 256) {
            int row = idx >> 5, j = idx & 31;           // j: float4 within row
            float4 v = hg[idx];
            int col = j * 4;
            uint32_t so = (uint32_t)(row * RB + (col >> 3) * 16 + (col & 7) * 2);
            *(uint32_t*)(smem + SM_AHI + so)     = pack_hi2(v.x, v.y);
            *(uint32_t*)(smem + SM_AHI + so + 4) = pack_hi2(v.z, v.w);
            *(uint32_t*)(smem + SM_ALO + so)     = pack_lo2(v.x, v.y);
            *(uint32_t*)(smem + SM_ALO + so + 4) = pack_lo2(v.z, v.w);
        }
    }
    __syncthreads();

    float acc[2][8][4];

    // ================= GEMM1: H1 = relu(A @ W1 + b1) =================
    #pragma unroll
    for (int mi = 0; mi < 2; mi++)
        #pragma unroll
        for (int ni = 0; ni < 8; ni++)
            #pragma unroll
            for (int q = 0; q < 4; q++) acc[mi][ni][q] = 0.0f;

    warp_gemm(sb, SM_AHI, SM_ALO, SM_W1H, SM_W1L, m0, n0, lane, acc);

    __syncthreads();   // everyone done reading A before we overwrite it

    // epilogue1: relu(+b1), split, write back into A_hi/A_lo
    {
        const float* b1s = (const float*)(smem + SM_B1);
        #pragma unroll
        for (int mi = 0; mi < 2; mi++) {
            int r0 = m0 + mi * 16 + (lane >> 2);
            #pragma unroll
            for (int ni = 0; ni < 8; ni++) {
                int c0 = n0 + ni * 8 + (lane & 3) * 2;
                float bb0 = b1s[c0], bb1 = b1s[c0 + 1];
                float v00 = fmaxf(acc[mi][ni][0] + bb0, 0.0f);
                float v01 = fmaxf(acc[mi][ni][1] + bb1, 0.0f);
                float v10 = fmaxf(acc[mi][ni][2] + bb0, 0.0f);
                float v11 = fmaxf(acc[mi][ni][3] + bb1, 0.0f);
                uint32_t so0 = (uint32_t)(r0 * RB + (c0 >> 3) * 16 + (c0 & 7) * 2);
                uint32_t so1 = so0 + 8 * RB;
                *(uint32_t*)(smem + SM_AHI + so0) = pack_hi2(v00, v01);
                *(uint32_t*)(smem + SM_ALO + so0) = pack_lo2(v00, v01);
                *(uint32_t*)(smem + SM_AHI + so1) = pack_hi2(v10, v11);
                *(uint32_t*)(smem + SM_ALO + so1) = pack_lo2(v10, v11);
            }
        }
    }
    __syncthreads();

    // ================= GEMM2: out = H1 @ W2 + b2 =================
    #pragma unroll
    for (int mi = 0; mi < 2; mi++)
        #pragma unroll
        for (int ni = 0; ni < 8; ni++)
            #pragma unroll
            for (int q = 0; q < 4; q++) acc[mi][ni][q] = 0.0f;

    warp_gemm(sb, SM_AHI, SM_ALO, SM_W2H, SM_W2L, m0, n0, lane, acc);

    // epilogue2: +b2, store fp32 to gmem (float2 per acc pair)
    {
        const float* b2s = (const float*)(smem + SM_B2);
        int base_m = blockIdx.x * MTILE + m0;
        #pragma unroll
        for (int mi = 0; mi < 2; mi++) {
            int gr0 = base_m + mi * 16 + (lane >> 2);
            int gr1 = gr0 + 8;
            #pragma unroll
            for (int ni = 0; ni < 8; ni++) {
                int c0 = n0 + ni * 8 + (lane & 3) * 2;
                float bb0 = b2s[c0], bb1 = b2s[c0 + 1];
                if (gr0 < N_NODES) {
                    float2 v = make_float2(acc[mi][ni][0] + bb0, acc[mi][ni][1] + bb1);
                    *(float2*)(out + (size_t)gr0 * D + c0) = v;
                }
                if (gr1 < N_NODES) {
                    float2 v = make_float2(acc[mi][ni][2] + bb0, acc[mi][ni][3] + bb1);
                    *(float2*)(out + (size_t)gr1 * D + c0) = v;
                }
            }
        }
    }
}

// ---------------------------------------------------------------------------
extern "C" void kernel_launch(void* const* d_in, const int* in_sizes, int n_in,
                              void* d_out, int out_size) {
    const float* x  = (const float*)d_in[0];
    const int*   ei = (const int*)d_in[1];
    const float* W1 = (const float*)d_in[2];
    const float* b1 = (const float*)d_in[3];
    const float* W2 = (const float*)d_in[4];
    const float* b2 = (const float*)d_in[5];
    float*       out = (float*)d_out;

    {
        int n4 = N_NODES * D / 4;
        init_kernel<<<(n4 + 255) / 256, 256>>>(x);
    }
    scatter_kernel<<<(E_EDGES + 7) / 8, 256>>>(x, ei);
    {
        cudaFuncSetAttribute(mlp_mma_kernel,
                             cudaFuncAttributeMaxDynamicSharedMemorySize, SM_TOTAL);
        mlp_mma_kernel<<<NBLK, 256, SM_TOTAL>>>(W1, b1, W2, b2, out);
    }
}

// round 5
// speedup vs baseline: 1.8067x; 1.2746x over previous
#include <cuda_runtime.h>
#include <cuda_bf16.h>
#include <cstdint>

#define N_NODES 100000
#define D 128
#define E_EDGES 640000

#define MTILE 128
#define NBLK 782                 // 782 * 128 = 100096
#define N_PAD 100096

#define CAP 40                   // in-degree capacity (Poisson(6.4): P(>40)~1e-12)
#define OVF_MAX 4096

__device__ float g_H[(size_t)N_PAD * D];
__device__ int   g_cnt[N_NODES];
__device__ int   g_list[(size_t)N_NODES * CAP];
__device__ int   g_ovf_cnt;
__device__ int2  g_ovf[OVF_MAX];

// ---- MLP smem layout (row stride 272B keeps ldmatrix conflict-free) ----
#define RB 272
#define T_BYTES (128 * RB)          // 34816 per tile
#define SM_AHI 0
#define SM_ALO (T_BYTES)
#define SM_W1H (2 * T_BYTES)
#define SM_W1L (3 * T_BYTES)
#define SM_W2H (4 * T_BYTES)
#define SM_W2L (5 * T_BYTES)
#define SM_B1  (6 * T_BYTES)
#define SM_B2  (6 * T_BYTES + 512)
#define SM_TOTAL (6 * T_BYTES + 1024)   // 209920

__device__ __align__(16) uint8_t g_Wprep[4 * T_BYTES];  // pre-swizzled split-bf16 W

// ---------------------------------------------------------------------------
// Kernel A: zero counters
// ---------------------------------------------------------------------------
__global__ void zero_kernel() {
    int i = blockIdx.x * blockDim.x + threadIdx.x;
    if (i < N_NODES / 4) ((int4*)g_cnt)[i] = make_int4(0, 0, 0, 0);
    if (i == 0) g_ovf_cnt = 0;
}

// ---------------------------------------------------------------------------
// Kernel B: bucket edges by destination (CSR-ish with fixed capacity)
// ---------------------------------------------------------------------------
__global__ void place_kernel(const int* __restrict__ ei) {
    int e = blockIdx.x * blockDim.x + threadIdx.x;
    if (e >= E_EDGES) return;
    int r = ei[e];              // source
    int c = ei[E_EDGES + e];    // destination
    int p = atomicAdd(&g_cnt[c], 1);
    if (p < CAP) {
        g_list[(size_t)c * CAP + p] = r;
    } else {
        int q = atomicAdd(&g_ovf_cnt, 1);
        if (q < OVF_MAX) g_ovf[q] = make_int2(r, c);
    }
}

// ---------------------------------------------------------------------------
// Kernel C: gather. One warp per node; lane owns a float4 (4 dims).
// H[n] = x[n] + sum_{src in list[n]} x[src]   (pure loads, no float atomics)
// ---------------------------------------------------------------------------
__global__ void __launch_bounds__(256)
gather_kernel(const float* __restrict__ x) {
    int gw = (blockIdx.x * blockDim.x + threadIdx.x) >> 5;
    int lane = threadIdx.x & 31;
    if (gw >= N_NODES) return;
    int cnt = g_cnt[gw];
    if (cnt > CAP) cnt = CAP;
    const float4* xr = (const float4*)x;
    float4 acc = __ldg(&xr[(size_t)gw * 32 + lane]);

    int mysrc = (lane < cnt) ? g_list[(size_t)gw * CAP + lane] : 0;
    int c2 = cnt < 32 ? cnt : 32;
    for (int i = 0; i < c2; i++) {
        int s = __shfl_sync(0xffffffffu, mysrc, i);
        float4 v = __ldg(&xr[(size_t)s * 32 + lane]);
        acc.x += v.x; acc.y += v.y; acc.z += v.z; acc.w += v.w;
    }
    for (int i = 32; i < cnt; i++) {
        int s = g_list[(size_t)gw * CAP + i];
        float4 v = __ldg(&xr[(size_t)s * 32 + lane]);
        acc.x += v.x; acc.y += v.y; acc.z += v.z; acc.w += v.w;
    }
    ((float4*)g_H)[(size_t)gw * 32 + lane] = acc;
}

// ---------------------------------------------------------------------------
// Kernel D: overflow fallback (normally 0 edges). One warp per overflow edge.
// ---------------------------------------------------------------------------
__global__ void ovf_kernel(const float* __restrict__ x) {
    int gw = (blockIdx.x * blockDim.x + threadIdx.x) >> 5;
    int lane = threadIdx.x & 31;
    int n = g_ovf_cnt;
    if (n > OVF_MAX) n = OVF_MAX;
    if (gw >= n) return;
    int2 e = g_ovf[gw];
    float4 v = ((const float4*)x)[(size_t)e.x * 32 + lane];
    atomicAdd(&((float4*)g_H)[(size_t)e.y * 32 + lane], v);
}

// ---------------------------------------------------------------------------
// Kernel E: one-shot weight prep — split-bf16, [n][k] layout with RB stride,
// stored to gmem so MLP CTAs just memcpy instead of converting 782x.
// ---------------------------------------------------------------------------
__global__ void wprep_kernel(const float* __restrict__ W1,
                             const float* __restrict__ W2) {
    int idx = blockIdx.x * blockDim.x + threadIdx.x;   // 0..16383
    if (idx >= D * D) return;
    int k = idx >> 7, n = idx & 127;
    uint32_t so = (uint32_t)(n * RB + (k >> 3) * 16 + (k & 7) * 2);
    float v1 = W1[idx];
    __nv_bfloat16 h1 = __float2bfloat16(v1);
    *(__nv_bfloat16*)(g_Wprep + so)               = h1;
    *(__nv_bfloat16*)(g_Wprep + T_BYTES + so)     =
        __float2bfloat16(v1 - __bfloat162float(h1));
    float v2 = W2[idx];
    __nv_bfloat16 h2 = __float2bfloat16(v2);
    *(__nv_bfloat16*)(g_Wprep + 2 * T_BYTES + so) = h2;
    *(__nv_bfloat16*)(g_Wprep + 3 * T_BYTES + so) =
        __float2bfloat16(v2 - __bfloat162float(h2));
}

// ---------------------------------------------------------------------------
// MLP on mma.sync bf16 with split-fp32 emulation (unchanged math from R4).
// ---------------------------------------------------------------------------
__device__ __forceinline__ uint32_t smem_u32(const void* p) {
    uint32_t a;
    asm("{ .reg .u64 t; cvta.to.shared.u64 t, %1; cvt.u32.u64 %0, t; }"
        : "=r"(a) : "l"(p));
    return a;
}

#define LDSM_X4(r0, r1, r2, r3, addr) \
    asm volatile("ldmatrix.sync.aligned.m8n8.x4.shared.b16 {%0,%1,%2,%3}, [%4];" \
        : "=r"(r0), "=r"(r1), "=r"(r2), "=r"(r3) : "r"(addr))

__device__ __forceinline__ void mma_bf16(float* d, const uint32_t* a, const uint32_t* b) {
    asm volatile(
        "mma.sync.aligned.m16n8k16.row.col.f32.bf16.bf16.f32 "
        "{%0,%1,%2,%3}, {%4,%5,%6,%7}, {%8,%9}, {%0,%1,%2,%3};"
        : "+f"(d[0]), "+f"(d[1]), "+f"(d[2]), "+f"(d[3])
        : "r"(a[0]), "r"(a[1]), "r"(a[2]), "r"(a[3]), "r"(b[0]), "r"(b[1]));
}

__device__ __forceinline__ uint32_t pack_hi2(float a, float b) {
    __nv_bfloat162 p(__float2bfloat16(a), __float2bfloat16(b));
    return *(uint32_t*)&p;
}
__device__ __forceinline__ uint32_t pack_lo2(float a, float b) {
    float ra = a - __bfloat162float(__float2bfloat16(a));
    float rb = b - __bfloat162float(__float2bfloat16(b));
    __nv_bfloat162 p(__float2bfloat16(ra), __float2bfloat16(rb));
    return *(uint32_t*)&p;
}

__device__ __forceinline__ void warp_gemm(
    uint32_t sb, uint32_t a_hi, uint32_t a_lo, uint32_t w_hi, uint32_t w_lo,
    int m0, int n0, int lane, float acc[2][8][4])
{
    const int li = lane & 7;
    const int sub = lane >> 3;
    const uint32_t a_off = (uint32_t)((li + (sub & 1) * 8) * RB + (sub >> 1) * 16);
    const uint32_t b_off = (uint32_t)((li + (sub >> 1) * 8) * RB + (sub & 1) * 16);

    #pragma unroll
    for (int ks = 0; ks < 8; ks++) {
        const uint32_t kchunk = (uint32_t)(ks * 32);
        uint32_t ah[2][4], al[2][4];
        #pragma unroll
        for (int mi = 0; mi < 2; mi++) {
            uint32_t base = (uint32_t)((m0 + mi * 16) * RB) + a_off + kchunk;
            LDSM_X4(ah[mi][0], ah[mi][1], ah[mi][2], ah[mi][3], sb + a_hi + base);
            LDSM_X4(al[mi][0], al[mi][1], al[mi][2], al[mi][3], sb + a_lo + base);
        }
        uint32_t bh[8][2], bl[8][2];
        #pragma unroll
        for (int nj = 0; nj < 4; nj++) {
            uint32_t base = (uint32_t)((n0 + nj * 16) * RB) + b_off + kchunk;
            uint32_t r0, r1, r2, r3;
            LDSM_X4(r0, r1, r2, r3, sb + w_hi + base);
            bh[nj * 2][0] = r0; bh[nj * 2][1] = r1;
            bh[nj * 2 + 1][0] = r2; bh[nj * 2 + 1][1] = r3;
            LDSM_X4(r0, r1, r2, r3, sb + w_lo + base);
            bl[nj * 2][0] = r0; bl[nj * 2][1] = r1;
            bl[nj * 2 + 1][0] = r2; bl[nj * 2 + 1][1] = r3;
        }
        #pragma unroll
        for (int mi = 0; mi < 2; mi++)
            #pragma unroll
            for (int ni = 0; ni < 8; ni++) {
                mma_bf16(acc[mi][ni], ah[mi], bh[ni]);
                mma_bf16(acc[mi][ni], ah[mi], bl[ni]);
                mma_bf16(acc[mi][ni], al[mi], bh[ni]);
            }
    }
}

__global__ void __launch_bounds__(256, 1)
mlp_mma_kernel(const float* __restrict__ b1, const float* __restrict__ b2,
               float* __restrict__ out) {
    extern __shared__ char smem[];
    const uint32_t sb = smem_u32(smem);
    const int tid = threadIdx.x;
    const int lane = tid & 31;
    const int wid = tid >> 5;
    const int m0 = (wid & 3) * 32;
    const int n0 = (wid >> 2) * 64;

    if (tid < 128) {
        ((float*)(smem + SM_B1))[tid] = b1[tid];
        ((float*)(smem + SM_B2))[tid] = b2[tid];
    }

    // copy pre-swizzled W tiles (4 * T_BYTES contiguous at SM_W1H)
    {
        const int4* wg = (const int4*)g_Wprep;
        int4* ws = (int4*)(smem + SM_W1H);
        #pragma unroll 4
        for (int i = tid; i < 4 * T_BYTES / 16; i += 256) ws[i] = wg[i];
    }

    // load + split A = H tile
    {
        const float4* hg = (const float4*)(g_H + (size_t)blockIdx.x * MTILE * D);
        for (int idx = tid; idx < 128 * 32; idx += 256) {
            int row = idx >> 5, j = idx & 31;
            float4 v = hg[idx];
            int col = j * 4;
            uint32_t so = (uint32_t)(row * RB + (col >> 3) * 16 + (col & 7) * 2);
            *(uint32_t*)(smem + SM_AHI + so)     = pack_hi2(v.x, v.y);
            *(uint32_t*)(smem + SM_AHI + so + 4) = pack_hi2(v.z, v.w);
            *(uint32_t*)(smem + SM_ALO + so)     = pack_lo2(v.x, v.y);
            *(uint32_t*)(smem + SM_ALO + so + 4) = pack_lo2(v.z, v.w);
        }
    }
    __syncthreads();

    float acc[2][8][4];

    // GEMM1: H1 = relu(A @ W1 + b1)
    #pragma unroll
    for (int mi = 0; mi < 2; mi++)
        #pragma unroll
        for (int ni = 0; ni < 8; ni++)
            #pragma unroll
            for (int q = 0; q < 4; q++) acc[mi][ni][q] = 0.0f;

    warp_gemm(sb, SM_AHI, SM_ALO, SM_W1H, SM_W1L, m0, n0, lane, acc);

    __syncthreads();

    {
        const float* b1s = (const float*)(smem + SM_B1);
        #pragma unroll
        for (int mi = 0; mi < 2; mi++) {
            int r0 = m0 + mi * 16 + (lane >> 2);
            #pragma unroll
            for (int ni = 0; ni < 8; ni++) {
                int c0 = n0 + ni * 8 + (lane & 3) * 2;
                float bb0 = b1s[c0], bb1 = b1s[c0 + 1];
                float v00 = fmaxf(acc[mi][ni][0] + bb0, 0.0f);
                float v01 = fmaxf(acc[mi][ni][1] + bb1, 0.0f);
                float v10 = fmaxf(acc[mi][ni][2] + bb0, 0.0f);
                float v11 = fmaxf(acc[mi][ni][3] + bb1, 0.0f);
                uint32_t so0 = (uint32_t)(r0 * RB + (c0 >> 3) * 16 + (c0 & 7) * 2);
                uint32_t so1 = so0 + 8 * RB;
                *(uint32_t*)(smem + SM_AHI + so0) = pack_hi2(v00, v01);
                *(uint32_t*)(smem + SM_ALO + so0) = pack_lo2(v00, v01);
                *(uint32_t*)(smem + SM_AHI + so1) = pack_hi2(v10, v11);
                *(uint32_t*)(smem + SM_ALO + so1) = pack_lo2(v10, v11);
            }
        }
    }
    __syncthreads();

    // GEMM2: out = H1 @ W2 + b2
    #pragma unroll
    for (int mi = 0; mi < 2; mi++)
        #pragma unroll
        for (int ni = 0; ni < 8; ni++)
            #pragma unroll
            for (int q = 0; q < 4; q++) acc[mi][ni][q] = 0.0f;

    warp_gemm(sb, SM_AHI, SM_ALO, SM_W2H, SM_W2L, m0, n0, lane, acc);

    {
        const float* b2s = (const float*)(smem + SM_B2);
        int base_m = blockIdx.x * MTILE + m0;
        #pragma unroll
        for (int mi = 0; mi < 2; mi++) {
            int gr0 = base_m + mi * 16 + (lane >> 2);
            int gr1 = gr0 + 8;
            #pragma unroll
            for (int ni = 0; ni < 8; ni++) {
                int c0 = n0 + ni * 8 + (lane & 3) * 2;
                float bb0 = b2s[c0], bb1 = b2s[c0 + 1];
                if (gr0 < N_NODES) {
                    float2 v = make_float2(acc[mi][ni][0] + bb0, acc[mi][ni][1] + bb1);
                    *(float2*)(out + (size_t)gr0 * D + c0) = v;
                }
                if (gr1 < N_NODES) {
                    float2 v = make_float2(acc[mi][ni][2] + bb0, acc[mi][ni][3] + bb1);
                    *(float2*)(out + (size_t)gr1 * D + c0) = v;
                }
            }
        }
    }
}

// ---------------------------------------------------------------------------
extern "C" void kernel_launch(void* const* d_in, const int* in_sizes, int n_in,
                              void* d_out, int out_size) {
    const float* x  = (const float*)d_in[0];
    const int*   ei = (const int*)d_in[1];
    const float* W1 = (const float*)d_in[2];
    const float* b1 = (const float*)d_in[3];
    const float* W2 = (const float*)d_in[4];
    const float* b2 = (const float*)d_in[5];
    float*       out = (float*)d_out;

    zero_kernel<<<(N_NODES / 4 + 255) / 256, 256>>>();
    wprep_kernel<<<(D * D + 255) / 256, 256>>>(W1, W2);
    place_kernel<<<(E_EDGES + 255) / 256, 256>>>(ei);
    gather_kernel<<<(N_NODES * 32 + 255) / 256, 256>>>(x);
    ovf_kernel<<<OVF_MAX / 8, 256>>>(x);
    {
        cudaFuncSetAttribute(mlp_mma_kernel,
                             cudaFuncAttributeMaxDynamicSharedMemorySize, SM_TOTAL);
        mlp_mma_kernel<<<NBLK, 256, SM_TOTAL>>>(b1, b2, out);
    }
}

// round 6
// speedup vs baseline: 2.0872x; 1.1553x over previous
#include <cuda_runtime.h>
#include <cuda_bf16.h>
#include <cstdint>

#define N_NODES 100000
#define D 128
#define E_EDGES 640000

#define MTILE 128
#define NBLK 782                 // 782 * 128 = 100096
#define N_PAD 100096
#define NSM 148

#define CAP 40                   // in-degree capacity (Poisson(6.4): P(>40)~1e-12)
#define OVF_MAX 4096

__device__ float g_H[(size_t)N_PAD * D];
__device__ int   g_cnt[N_NODES];
__device__ int   g_list[(size_t)N_NODES * CAP];
__device__ int   g_ovf_cnt;
__device__ int2  g_ovf[OVF_MAX];

// ---- MLP smem layout (row stride 272B keeps ldmatrix conflict-free) ----
#define RB 272
#define T_BYTES (128 * RB)          // 34816 per tile
#define SM_AHI 0
#define SM_ALO (T_BYTES)
#define SM_W1H (2 * T_BYTES)
#define SM_W1L (3 * T_BYTES)
#define SM_W2H (4 * T_BYTES)
#define SM_W2L (5 * T_BYTES)
#define SM_B1  (6 * T_BYTES)
#define SM_B2  (6 * T_BYTES + 512)
#define SM_TOTAL (6 * T_BYTES + 1024)   // 209920

__device__ __align__(16) uint8_t g_Wprep[4 * T_BYTES];  // pre-swizzled split-bf16 W

// ---------------------------------------------------------------------------
// Kernel A: zero counters + one-shot weight prep (split-bf16, [n][k], RB-stride)
// ---------------------------------------------------------------------------
__global__ void prep_kernel(const float* __restrict__ W1,
                            const float* __restrict__ W2) {
    int i = blockIdx.x * blockDim.x + threadIdx.x;
    if (i < N_NODES / 4) ((int4*)g_cnt)[i] = make_int4(0, 0, 0, 0);
    if (i == 0) g_ovf_cnt = 0;
    if (i < D * D) {
        int k = i >> 7, n = i & 127;
        uint32_t so = (uint32_t)(n * RB + (k >> 3) * 16 + (k & 7) * 2);
        float v1 = W1[i];
        __nv_bfloat16 h1 = __float2bfloat16(v1);
        *(__nv_bfloat16*)(g_Wprep + so)               = h1;
        *(__nv_bfloat16*)(g_Wprep + T_BYTES + so)     =
            __float2bfloat16(v1 - __bfloat162float(h1));
        float v2 = W2[i];
        __nv_bfloat16 h2 = __float2bfloat16(v2);
        *(__nv_bfloat16*)(g_Wprep + 2 * T_BYTES + so) = h2;
        *(__nv_bfloat16*)(g_Wprep + 3 * T_BYTES + so) =
            __float2bfloat16(v2 - __bfloat162float(h2));
    }
}

// ---------------------------------------------------------------------------
// Kernel B: bucket edges by destination
// ---------------------------------------------------------------------------
__global__ void place_kernel(const int* __restrict__ ei) {
    int e = blockIdx.x * blockDim.x + threadIdx.x;
    if (e >= E_EDGES) return;
    int r = ei[e];              // source
    int c = ei[E_EDGES + e];    // destination
    int p = atomicAdd(&g_cnt[c], 1);
    if (p < CAP) {
        g_list[(size_t)c * CAP + p] = r;
    } else {
        int q = atomicAdd(&g_ovf_cnt, 1);
        if (q < OVF_MAX) g_ovf[q] = make_int2(r, c);
    }
}

// ---------------------------------------------------------------------------
// Kernel C: gather. One warp per node; lane owns a float4 (4 dims).
// 4 independent accumulators -> 4 LDG.128 in flight per warp.
// ---------------------------------------------------------------------------
__global__ void __launch_bounds__(256)
gather_kernel(const float* __restrict__ x) {
    int gw = (blockIdx.x * blockDim.x + threadIdx.x) >> 5;
    int lane = threadIdx.x & 31;
    if (gw >= N_NODES) return;
    int cnt = g_cnt[gw];
    if (cnt > CAP) cnt = CAP;
    const float4* xr = (const float4*)x;
    float4 a0 = __ldg(&xr[(size_t)gw * 32 + lane]);
    float4 a1 = make_float4(0.f, 0.f, 0.f, 0.f);
    float4 a2 = make_float4(0.f, 0.f, 0.f, 0.f);
    float4 a3 = make_float4(0.f, 0.f, 0.f, 0.f);

    int mysrc = (lane < cnt) ? g_list[(size_t)gw * CAP + lane] : 0;
    int c2 = cnt < 32 ? cnt : 32;
    int i = 0;
    for (; i + 4 <= c2; i += 4) {
        int s0 = __shfl_sync(0xffffffffu, mysrc, i);
        int s1 = __shfl_sync(0xffffffffu, mysrc, i + 1);
        int s2 = __shfl_sync(0xffffffffu, mysrc, i + 2);
        int s3 = __shfl_sync(0xffffffffu, mysrc, i + 3);
        float4 v0 = __ldg(&xr[(size_t)s0 * 32 + lane]);
        float4 v1 = __ldg(&xr[(size_t)s1 * 32 + lane]);
        float4 v2 = __ldg(&xr[(size_t)s2 * 32 + lane]);
        float4 v3 = __ldg(&xr[(size_t)s3 * 32 + lane]);
        a0.x += v0.x; a0.y += v0.y; a0.z += v0.z; a0.w += v0.w;
        a1.x += v1.x; a1.y += v1.y; a1.z += v1.z; a1.w += v1.w;
        a2.x += v2.x; a2.y += v2.y; a2.z += v2.z; a2.w += v2.w;
        a3.x += v3.x; a3.y += v3.y; a3.z += v3.z; a3.w += v3.w;
    }
    for (; i < c2; i++) {
        int s = __shfl_sync(0xffffffffu, mysrc, i);
        float4 v = __ldg(&xr[(size_t)s * 32 + lane]);
        a0.x += v.x; a0.y += v.y; a0.z += v.z; a0.w += v.w;
    }
    for (int j = 32; j < cnt; j++) {                    // ultra-rare
        int s = g_list[(size_t)gw * CAP + j];
        float4 v = __ldg(&xr[(size_t)s * 32 + lane]);
        a0.x += v.x; a0.y += v.y; a0.z += v.z; a0.w += v.w;
    }
    float4 acc;
    acc.x = (a0.x + a1.x) + (a2.x + a3.x);
    acc.y = (a0.y + a1.y) + (a2.y + a3.y);
    acc.z = (a0.z + a1.z) + (a2.z + a3.z);
    acc.w = (a0.w + a1.w) + (a2.w + a3.w);
    ((float4*)g_H)[(size_t)gw * 32 + lane] = acc;
}

// ---------------------------------------------------------------------------
// Kernel D: overflow fallback (normally 0 edges).
// ---------------------------------------------------------------------------
__global__ void ovf_kernel(const float* __restrict__ x) {
    int gw = (blockIdx.x * blockDim.x + threadIdx.x) >> 5;
    int lane = threadIdx.x & 31;
    int n = g_ovf_cnt;
    if (n > OVF_MAX) n = OVF_MAX;
    if (gw >= n) return;
    int2 e = g_ovf[gw];
    float4 v = ((const float4*)x)[(size_t)e.x * 32 + lane];
    atomicAdd(&((float4*)g_H)[(size_t)e.y * 32 + lane], v);
}

// ---------------------------------------------------------------------------
// MLP on mma.sync bf16 with split-fp32 emulation — PERSISTENT version.
// ---------------------------------------------------------------------------
__device__ __forceinline__ uint32_t smem_u32(const void* p) {
    uint32_t a;
    asm("{ .reg .u64 t; cvta.to.shared.u64 t, %1; cvt.u32.u64 %0, t; }"
        : "=r"(a) : "l"(p));
    return a;
}

#define LDSM_X4(r0, r1, r2, r3, addr) \
    asm volatile("ldmatrix.sync.aligned.m8n8.x4.shared.b16 {%0,%1,%2,%3}, [%4];" \
        : "=r"(r0), "=r"(r1), "=r"(r2), "=r"(r3) : "r"(addr))

__device__ __forceinline__ void mma_bf16(float* d, const uint32_t* a, const uint32_t* b) {
    asm volatile(
        "mma.sync.aligned.m16n8k16.row.col.f32.bf16.bf16.f32 "
        "{%0,%1,%2,%3}, {%4,%5,%6,%7}, {%8,%9}, {%0,%1,%2,%3};"
        : "+f"(d[0]), "+f"(d[1]), "+f"(d[2]), "+f"(d[3])
        : "r"(a[0]), "r"(a[1]), "r"(a[2]), "r"(a[3]), "r"(b[0]), "r"(b[1]));
}

__device__ __forceinline__ uint32_t pack_hi2(float a, float b) {
    __nv_bfloat162 p(__float2bfloat16(a), __float2bfloat16(b));
    return *(uint32_t*)&p;
}
__device__ __forceinline__ uint32_t pack_lo2(float a, float b) {
    float ra = a - __bfloat162float(__float2bfloat16(a));
    float rb = b - __bfloat162float(__float2bfloat16(b));
    __nv_bfloat162 p(__float2bfloat16(ra), __float2bfloat16(rb));
    return *(uint32_t*)&p;
}

__device__ __forceinline__ void warp_gemm(
    uint32_t sb, uint32_t a_hi, uint32_t a_lo, uint32_t w_hi, uint32_t w_lo,
    int m0, int n0, int lane, float acc[2][8][4])
{
    const int li = lane & 7;
    const int sub = lane >> 3;
    const uint32_t a_off = (uint32_t)((li + (sub & 1) * 8) * RB + (sub >> 1) * 16);
    const uint32_t b_off = (uint32_t)((li + (sub >> 1) * 8) * RB + (sub & 1) * 16);

    #pragma unroll
    for (int ks = 0; ks < 8; ks++) {
        const uint32_t kchunk = (uint32_t)(ks * 32);
        uint32_t ah[2][4], al[2][4];
        #pragma unroll
        for (int mi = 0; mi < 2; mi++) {
            uint32_t base = (uint32_t)((m0 + mi * 16) * RB) + a_off + kchunk;
            LDSM_X4(ah[mi][0], ah[mi][1], ah[mi][2], ah[mi][3], sb + a_hi + base);
            LDSM_X4(al[mi][0], al[mi][1], al[mi][2], al[mi][3], sb + a_lo + base);
        }
        uint32_t bh[8][2], bl[8][2];
        #pragma unroll
        for (int nj = 0; nj < 4; nj++) {
            uint32_t base = (uint32_t)((n0 + nj * 16) * RB) + b_off + kchunk;
            uint32_t r0, r1, r2, r3;
            LDSM_X4(r0, r1, r2, r3, sb + w_hi + base);
            bh[nj * 2][0] = r0; bh[nj * 2][1] = r1;
            bh[nj * 2 + 1][0] = r2; bh[nj * 2 + 1][1] = r3;
            LDSM_X4(r0, r1, r2, r3, sb + w_lo + base);
            bl[nj * 2][0] = r0; bl[nj * 2][1] = r1;
            bl[nj * 2 + 1][0] = r2; bl[nj * 2 + 1][1] = r3;
        }
        #pragma unroll
        for (int mi = 0; mi < 2; mi++)
            #pragma unroll
            for (int ni = 0; ni < 8; ni++) {
                mma_bf16(acc[mi][ni], ah[mi], bh[ni]);
                mma_bf16(acc[mi][ni], ah[mi], bl[ni]);
                mma_bf16(acc[mi][ni], al[mi], bh[ni]);
            }
    }
}

__global__ void __launch_bounds__(256, 1)
mlp_mma_kernel(const float* __restrict__ b1, const float* __restrict__ b2,
               float* __restrict__ out) {
    extern __shared__ char smem[];
    const uint32_t sb = smem_u32(smem);
    const int tid = threadIdx.x;
    const int lane = tid & 31;
    const int wid = tid >> 5;
    const int m0 = (wid & 3) * 32;
    const int n0 = (wid >> 2) * 64;

    if (tid < 128) {
        ((float*)(smem + SM_B1))[tid] = b1[tid];
        ((float*)(smem + SM_B2))[tid] = b2[tid];
    }
    // stage pre-swizzled W tiles ONCE (persistent CTA)
    {
        const int4* wg = (const int4*)g_Wprep;
        int4* ws = (int4*)(smem + SM_W1H);
        #pragma unroll 4
        for (int i = tid; i < 4 * T_BYTES / 16; i += 256) ws[i] = wg[i];
    }

    for (int t = blockIdx.x; t < NBLK; t += NSM) {
        // load + split A = H tile
        {
            const float4* hg = (const float4*)(g_H + (size_t)t * MTILE * D);
            for (int idx = tid; idx < 128 * 32; idx += 256) {
                int row = idx >> 5, j = idx & 31;
                float4 v = hg[idx];
                int col = j * 4;
                uint32_t so = (uint32_t)(row * RB + (col >> 3) * 16 + (col & 7) * 2);
                *(uint32_t*)(smem + SM_AHI + so)     = pack_hi2(v.x, v.y);
                *(uint32_t*)(smem + SM_AHI + so + 4) = pack_hi2(v.z, v.w);
                *(uint32_t*)(smem + SM_ALO + so)     = pack_lo2(v.x, v.y);
                *(uint32_t*)(smem + SM_ALO + so + 4) = pack_lo2(v.z, v.w);
            }
        }
        __syncthreads();

        float acc[2][8][4];

        // GEMM1: H1 = relu(A @ W1 + b1)
        #pragma unroll
        for (int mi = 0; mi < 2; mi++)
            #pragma unroll
            for (int ni = 0; ni < 8; ni++)
                #pragma unroll
                for (int q = 0; q < 4; q++) acc[mi][ni][q] = 0.0f;

        warp_gemm(sb, SM_AHI, SM_ALO, SM_W1H, SM_W1L, m0, n0, lane, acc);

        __syncthreads();

        {
            const float* b1s = (const float*)(smem + SM_B1);
            #pragma unroll
            for (int mi = 0; mi < 2; mi++) {
                int r0 = m0 + mi * 16 + (lane >> 2);
                #pragma unroll
                for (int ni = 0; ni < 8; ni++) {
                    int c0 = n0 + ni * 8 + (lane & 3) * 2;
                    float bb0 = b1s[c0], bb1 = b1s[c0 + 1];
                    float v00 = fmaxf(acc[mi][ni][0] + bb0, 0.0f);
                    float v01 = fmaxf(acc[mi][ni][1] + bb1, 0.0f);
                    float v10 = fmaxf(acc[mi][ni][2] + bb0, 0.0f);
                    float v11 = fmaxf(acc[mi][ni][3] + bb1, 0.0f);
                    uint32_t so0 = (uint32_t)(r0 * RB + (c0 >> 3) * 16 + (c0 & 7) * 2);
                    uint32_t so1 = so0 + 8 * RB;
                    *(uint32_t*)(smem + SM_AHI + so0) = pack_hi2(v00, v01);
                    *(uint32_t*)(smem + SM_ALO + so0) = pack_lo2(v00, v01);
                    *(uint32_t*)(smem + SM_AHI + so1) = pack_hi2(v10, v11);
                    *(uint32_t*)(smem + SM_ALO + so1) = pack_lo2(v10, v11);
                }
            }
        }
        __syncthreads();

        // GEMM2: out = H1 @ W2 + b2
        #pragma unroll
        for (int mi = 0; mi < 2; mi++)
            #pragma unroll
            for (int ni = 0; ni < 8; ni++)
                #pragma unroll
                for (int q = 0; q < 4; q++) acc[mi][ni][q] = 0.0f;

        warp_gemm(sb, SM_AHI, SM_ALO, SM_W2H, SM_W2L, m0, n0, lane, acc);

        {
            const float* b2s = (const float*)(smem + SM_B2);
            int base_m = t * MTILE + m0;
            #pragma unroll
            for (int mi = 0; mi < 2; mi++) {
                int gr0 = base_m + mi * 16 + (lane >> 2);
                int gr1 = gr0 + 8;
                #pragma unroll
                for (int ni = 0; ni < 8; ni++) {
                    int c0 = n0 + ni * 8 + (lane & 3) * 2;
                    float bb0 = b2s[c0], bb1 = b2s[c0 + 1];
                    if (gr0 < N_NODES) {
                        float2 v = make_float2(acc[mi][ni][0] + bb0, acc[mi][ni][1] + bb1);
                        *(float2*)(out + (size_t)gr0 * D + c0) = v;
                    }
                    if (gr1 < N_NODES) {
                        float2 v = make_float2(acc[mi][ni][2] + bb0, acc[mi][ni][3] + bb1);
                        *(float2*)(out + (size_t)gr1 * D + c0) = v;
                    }
                }
            }
        }
        __syncthreads();   // A reused next iteration
    }
}

// ---------------------------------------------------------------------------
extern "C" void kernel_launch(void* const* d_in, const int* in_sizes, int n_in,
                              void* d_out, int out_size) {
    const float* x  = (const float*)d_in[0];
    const int*   ei = (const int*)d_in[1];
    const float* W1 = (const float*)d_in[2];
    const float* b1 = (const float*)d_in[3];
    const float* W2 = (const float*)d_in[4];
    const float* b2 = (const float*)d_in[5];
    float*       out = (float*)d_out;

    prep_kernel<<<(N_NODES / 4 + 255) / 256, 256>>>(W1, W2);
    place_kernel<<<(E_EDGES + 255) / 256, 256>>>(ei);
    gather_kernel<<<(N_NODES * 32 + 255) / 256, 256>>>(x);
    ovf_kernel<<<OVF_MAX / 8, 256>>>(x);
    {
        cudaFuncSetAttribute(mlp_mma_kernel,
                             cudaFuncAttributeMaxDynamicSharedMemorySize, SM_TOTAL);
        mlp_mma_kernel<<<NSM, 256, SM_TOTAL>>>(b1, b2, out);
    }
}

// round 7
// speedup vs baseline: 2.6035x; 1.2474x over previous
#include <cuda_runtime.h>
#include <cuda_bf16.h>
#include <cuda_fp16.h>
#include <cstdint>

#define N_NODES 100000
#define D 128
#define E_EDGES 640000

#define MTILE 128
#define NBLK 782                 // 782 * 128 = 100096
#define N_PAD 100096
#define NSM 148

#define CAP 40                   // in-degree capacity (Poisson(6.4): P(>40)~1e-12)
#define OVF_MAX 4096

__device__ float g_H[(size_t)N_PAD * D];
__device__ int   g_cnt[N_NODES];
__device__ int   g_list[(size_t)N_NODES * CAP];
__device__ int   g_ovf_cnt;
__device__ int2  g_ovf[OVF_MAX];

// ---- MLP smem layout (row stride 272B keeps ldmatrix conflict-free) ----
#define RB 272
#define T_BYTES (128 * RB)          // 34816 per tile
#define SM_A   0
#define SM_W1  (T_BYTES)
#define SM_W2  (2 * T_BYTES)
#define SM_B1  (3 * T_BYTES)
#define SM_B2  (3 * T_BYTES + 512)
#define SM_TOTAL (3 * T_BYTES + 1024)   // 105472

__device__ __align__(16) uint8_t g_Wprep[2 * T_BYTES];  // fp16 W1,W2 pre-swizzled

// ---------------------------------------------------------------------------
// Kernel A: zero counters + one-shot weight prep (fp16, [n][k], RB-stride)
// ---------------------------------------------------------------------------
__global__ void prep_kernel(const float* __restrict__ W1,
                            const float* __restrict__ W2) {
    int i = blockIdx.x * blockDim.x + threadIdx.x;
    if (i < N_NODES / 4) ((int4*)g_cnt)[i] = make_int4(0, 0, 0, 0);
    if (i == 0) g_ovf_cnt = 0;
    if (i < D * D) {
        int k = i >> 7, n = i & 127;
        uint32_t so = (uint32_t)(n * RB + (k >> 3) * 16 + (k & 7) * 2);
        *(__half*)(g_Wprep + so)           = __float2half_rn(W1[i]);
        *(__half*)(g_Wprep + T_BYTES + so) = __float2half_rn(W2[i]);
    }
}

// ---------------------------------------------------------------------------
// Kernel B: bucket edges by destination
// ---------------------------------------------------------------------------
__global__ void place_kernel(const int* __restrict__ ei) {
    int e = blockIdx.x * blockDim.x + threadIdx.x;
    if (e >= E_EDGES) return;
    int r = ei[e];              // source
    int c = ei[E_EDGES + e];    // destination
    int p = atomicAdd(&g_cnt[c], 1);
    if (p < CAP) {
        g_list[(size_t)c * CAP + p] = r;
    } else {
        int q = atomicAdd(&g_ovf_cnt, 1);
        if (q < OVF_MAX) g_ovf[q] = make_int2(r, c);
    }
}

// ---------------------------------------------------------------------------
// Kernel C: gather. One warp per node; lane owns a float4 (4 dims).
// 4 independent accumulators -> 4 LDG.128 in flight per warp.
// ---------------------------------------------------------------------------
__global__ void __launch_bounds__(256)
gather_kernel(const float* __restrict__ x) {
    int gw = (blockIdx.x * blockDim.x + threadIdx.x) >> 5;
    int lane = threadIdx.x & 31;
    if (gw >= N_NODES) return;
    int cnt = g_cnt[gw];
    if (cnt > CAP) cnt = CAP;
    const float4* xr = (const float4*)x;
    float4 a0 = __ldg(&xr[(size_t)gw * 32 + lane]);
    float4 a1 = make_float4(0.f, 0.f, 0.f, 0.f);
    float4 a2 = make_float4(0.f, 0.f, 0.f, 0.f);
    float4 a3 = make_float4(0.f, 0.f, 0.f, 0.f);

    int mysrc = (lane < cnt) ? g_list[(size_t)gw * CAP + lane] : 0;
    int c2 = cnt < 32 ? cnt : 32;
    int i = 0;
    for (; i + 4 <= c2; i += 4) {
        int s0 = __shfl_sync(0xffffffffu, mysrc, i);
        int s1 = __shfl_sync(0xffffffffu, mysrc, i + 1);
        int s2 = __shfl_sync(0xffffffffu, mysrc, i + 2);
        int s3 = __shfl_sync(0xffffffffu, mysrc, i + 3);
        float4 v0 = __ldg(&xr[(size_t)s0 * 32 + lane]);
        float4 v1 = __ldg(&xr[(size_t)s1 * 32 + lane]);
        float4 v2 = __ldg(&xr[(size_t)s2 * 32 + lane]);
        float4 v3 = __ldg(&xr[(size_t)s3 * 32 + lane]);
        a0.x += v0.x; a0.y += v0.y; a0.z += v0.z; a0.w += v0.w;
        a1.x += v1.x; a1.y += v1.y; a1.z += v1.z; a1.w += v1.w;
        a2.x += v2.x; a2.y += v2.y; a2.z += v2.z; a2.w += v2.w;
        a3.x += v3.x; a3.y += v3.y; a3.z += v3.z; a3.w += v3.w;
    }
    for (; i < c2; i++) {
        int s = __shfl_sync(0xffffffffu, mysrc, i);
        float4 v = __ldg(&xr[(size_t)s * 32 + lane]);
        a0.x += v.x; a0.y += v.y; a0.z += v.z; a0.w += v.w;
    }
    for (int j = 32; j < cnt; j++) {                    // ultra-rare
        int s = g_list[(size_t)gw * CAP + j];
        float4 v = __ldg(&xr[(size_t)s * 32 + lane]);
        a0.x += v.x; a0.y += v.y; a0.z += v.z; a0.w += v.w;
    }
    float4 acc;
    acc.x = (a0.x + a1.x) + (a2.x + a3.x);
    acc.y = (a0.y + a1.y) + (a2.y + a3.y);
    acc.z = (a0.z + a1.z) + (a2.z + a3.z);
    acc.w = (a0.w + a1.w) + (a2.w + a3.w);
    ((float4*)g_H)[(size_t)gw * 32 + lane] = acc;
}

// ---------------------------------------------------------------------------
// Kernel D: overflow fallback (normally 0 edges). Single block, grid-stride.
// ---------------------------------------------------------------------------
__global__ void ovf_kernel(const float* __restrict__ x) {
    int lane = threadIdx.x & 31;
    int wid  = threadIdx.x >> 5;
    int n = g_ovf_cnt;
    if (n > OVF_MAX) n = OVF_MAX;
    for (int e = wid; e < n; e += 8) {
        int2 ed = g_ovf[e];
        float4 v = ((const float4*)x)[(size_t)ed.x * 32 + lane];
        atomicAdd(&((float4*)g_H)[(size_t)ed.y * 32 + lane], v);
    }
}

// ---------------------------------------------------------------------------
// MLP: persistent, single-pass fp16 mma.sync (m16n8k16, f32 accumulate).
// ---------------------------------------------------------------------------
__device__ __forceinline__ uint32_t smem_u32(const void* p) {
    uint32_t a;
    asm("{ .reg .u64 t; cvta.to.shared.u64 t, %1; cvt.u32.u64 %0, t; }"
        : "=r"(a) : "l"(p));
    return a;
}

#define LDSM_X4(r0, r1, r2, r3, addr) \
    asm volatile("ldmatrix.sync.aligned.m8n8.x4.shared.b16 {%0,%1,%2,%3}, [%4];" \
        : "=r"(r0), "=r"(r1), "=r"(r2), "=r"(r3) : "r"(addr))

__device__ __forceinline__ void mma_f16(float* d, const uint32_t* a, const uint32_t* b) {
    asm volatile(
        "mma.sync.aligned.m16n8k16.row.col.f32.f16.f16.f32 "
        "{%0,%1,%2,%3}, {%4,%5,%6,%7}, {%8,%9}, {%0,%1,%2,%3};"
        : "+f"(d[0]), "+f"(d[1]), "+f"(d[2]), "+f"(d[3])
        : "r"(a[0]), "r"(a[1]), "r"(a[2]), "r"(a[3]), "r"(b[0]), "r"(b[1]));
}

__device__ __forceinline__ uint32_t packh2(float a, float b) {
    __half2 p = __floats2half2_rn(a, b);
    return *(uint32_t*)&p;
}

// Single-pass warp GEMM: acc += A @ W over K=128. Warp tile 32m x 64n.
__device__ __forceinline__ void warp_gemm(
    uint32_t sb, uint32_t a_t, uint32_t w_t,
    int m0, int n0, int lane, float acc[2][8][4])
{
    const int li = lane & 7;
    const int sub = lane >> 3;
    const uint32_t a_off = (uint32_t)((li + (sub & 1) * 8) * RB + (sub >> 1) * 16);
    const uint32_t b_off = (uint32_t)((li + (sub >> 1) * 8) * RB + (sub & 1) * 16);

    #pragma unroll
    for (int ks = 0; ks < 8; ks++) {
        const uint32_t kchunk = (uint32_t)(ks * 32);
        uint32_t ah[2][4];
        #pragma unroll
        for (int mi = 0; mi < 2; mi++) {
            uint32_t base = (uint32_t)((m0 + mi * 16) * RB) + a_off + kchunk;
            LDSM_X4(ah[mi][0], ah[mi][1], ah[mi][2], ah[mi][3], sb + a_t + base);
        }
        uint32_t bh[8][2];
        #pragma unroll
        for (int nj = 0; nj < 4; nj++) {
            uint32_t base = (uint32_t)((n0 + nj * 16) * RB) + b_off + kchunk;
            uint32_t r0, r1, r2, r3;
            LDSM_X4(r0, r1, r2, r3, sb + w_t + base);
            bh[nj * 2][0] = r0; bh[nj * 2][1] = r1;
            bh[nj * 2 + 1][0] = r2; bh[nj * 2 + 1][1] = r3;
        }
        #pragma unroll
        for (int mi = 0; mi < 2; mi++)
            #pragma unroll
            for (int ni = 0; ni < 8; ni++)
                mma_f16(acc[mi][ni], ah[mi], bh[ni]);
    }
}

__global__ void __launch_bounds__(256, 1)
mlp_mma_kernel(const float* __restrict__ b1, const float* __restrict__ b2,
               float* __restrict__ out) {
    extern __shared__ char smem[];
    const uint32_t sb = smem_u32(smem);
    const int tid = threadIdx.x;
    const int lane = tid & 31;
    const int wid = tid >> 5;
    const int m0 = (wid & 3) * 32;
    const int n0 = (wid >> 2) * 64;

    if (tid < 128) {
        ((float*)(smem + SM_B1))[tid] = b1[tid];
        ((float*)(smem + SM_B2))[tid] = b2[tid];
    }
    // stage pre-swizzled fp16 W tiles ONCE (persistent CTA)
    {
        const int4* wg = (const int4*)g_Wprep;
        int4* ws = (int4*)(smem + SM_W1);
        #pragma unroll 4
        for (int i = tid; i < 2 * T_BYTES / 16; i += 256) ws[i] = wg[i];
    }

    for (int t = blockIdx.x; t < NBLK; t += NSM) {
        // load + convert A = H tile to fp16
        {
            const float4* hg = (const float4*)(g_H + (size_t)t * MTILE * D);
            for (int idx = tid; idx < 128 * 32; idx += 256) {
                int row = idx >> 5, j = idx & 31;
                float4 v = hg[idx];
                int col = j * 4;
                uint32_t so = (uint32_t)(row * RB + (col >> 3) * 16 + (col & 7) * 2);
                *(uint32_t*)(smem + SM_A + so)     = packh2(v.x, v.y);
                *(uint32_t*)(smem + SM_A + so + 4) = packh2(v.z, v.w);
            }
        }
        __syncthreads();

        float acc[2][8][4];

        // GEMM1: H1 = relu(A @ W1 + b1)
        #pragma unroll
        for (int mi = 0; mi < 2; mi++)
            #pragma unroll
            for (int ni = 0; ni < 8; ni++)
                #pragma unroll
                for (int q = 0; q < 4; q++) acc[mi][ni][q] = 0.0f;

        warp_gemm(sb, SM_A, SM_W1, m0, n0, lane, acc);

        __syncthreads();

        {
            const float* b1s = (const float*)(smem + SM_B1);
            #pragma unroll
            for (int mi = 0; mi < 2; mi++) {
                int r0 = m0 + mi * 16 + (lane >> 2);
                #pragma unroll
                for (int ni = 0; ni < 8; ni++) {
                    int c0 = n0 + ni * 8 + (lane & 3) * 2;
                    float bb0 = b1s[c0], bb1 = b1s[c0 + 1];
                    float v00 = fmaxf(acc[mi][ni][0] + bb0, 0.0f);
                    float v01 = fmaxf(acc[mi][ni][1] + bb1, 0.0f);
                    float v10 = fmaxf(acc[mi][ni][2] + bb0, 0.0f);
                    float v11 = fmaxf(acc[mi][ni][3] + bb1, 0.0f);
                    uint32_t so0 = (uint32_t)(r0 * RB + (c0 >> 3) * 16 + (c0 & 7) * 2);
                    uint32_t so1 = so0 + 8 * RB;
                    *(uint32_t*)(smem + SM_A + so0) = packh2(v00, v01);
                    *(uint32_t*)(smem + SM_A + so1) = packh2(v10, v11);
                }
            }
        }
        __syncthreads();

        // GEMM2: out = H1 @ W2 + b2
        #pragma unroll
        for (int mi = 0; mi < 2; mi++)
            #pragma unroll
            for (int ni = 0; ni < 8; ni++)
                #pragma unroll
                for (int q = 0; q < 4; q++) acc[mi][ni][q] = 0.0f;

        warp_gemm(sb, SM_A, SM_W2, m0, n0, lane, acc);

        {
            const float* b2s = (const float*)(smem + SM_B2);
            int base_m = t * MTILE + m0;
            #pragma unroll
            for (int mi = 0; mi < 2; mi++) {
                int gr0 = base_m + mi * 16 + (lane >> 2);
                int gr1 = gr0 + 8;
                #pragma unroll
                for (int ni = 0; ni < 8; ni++) {
                    int c0 = n0 + ni * 8 + (lane & 3) * 2;
                    float bb0 = b2s[c0], bb1 = b2s[c0 + 1];
                    if (gr0 < N_NODES) {
                        float2 v = make_float2(acc[mi][ni][0] + bb0, acc[mi][ni][1] + bb1);
                        *(float2*)(out + (size_t)gr0 * D + c0) = v;
                    }
                    if (gr1 < N_NODES) {
                        float2 v = make_float2(acc[mi][ni][2] + bb0, acc[mi][ni][3] + bb1);
                        *(float2*)(out + (size_t)gr1 * D + c0) = v;
                    }
                }
            }
        }
        __syncthreads();   // A reused next iteration
    }
}

// ---------------------------------------------------------------------------
extern "C" void kernel_launch(void* const* d_in, const int* in_sizes, int n_in,
                              void* d_out, int out_size) {
    const float* x  = (const float*)d_in[0];
    const int*   ei = (const int*)d_in[1];
    const float* W1 = (const float*)d_in[2];
    const float* b1 = (const float*)d_in[3];
    const float* W2 = (const float*)d_in[4];
    const float* b2 = (const float*)d_in[5];
    float*       out = (float*)d_out;

    prep_kernel<<<(N_NODES / 4 + 255) / 256, 256>>>(W1, W2);
    place_kernel<<<(E_EDGES + 255) / 256, 256>>>(ei);
    gather_kernel<<<(N_NODES * 32 + 255) / 256, 256>>>(x);
    ovf_kernel<<<1, 256>>>(x);
    {
        cudaFuncSetAttribute(mlp_mma_kernel,
                             cudaFuncAttributeMaxDynamicSharedMemorySize, SM_TOTAL);
        mlp_mma_kernel<<<NSM, 256, SM_TOTAL>>>(b1, b2, out);
    }
}

// round 8
// speedup vs baseline: 3.2865x; 1.2623x over previous
#include <cuda_runtime.h>
#include <cuda_fp16.h>
#include <cstdint>

#define N_NODES 100000
#define D 128
#define E_EDGES 640000

#define MTILE 128
#define NBLK 782                 // 782 * 128 = 100096
#define NSM 148

#define CAP 40                   // in-degree capacity (Poisson(6.4): P(>40)~1e-12)
#define OVF_MAX 4096

// ---- MMA smem tile layout (row stride 272B keeps ldmatrix conflict-free) ----
#define RB 272
#define T_BYTES (128 * RB)          // 34816 per tile

__device__ int   g_cnt[N_NODES];
__device__ int   g_list[(size_t)N_NODES * CAP];
__device__ int   g_ovf_cnt;
__device__ int2  g_ovf[OVF_MAX];
// H in fp16, pre-swizzled MMA layout, one T_BYTES block per 128-row tile
__device__ __align__(16) uint8_t g_Hh[(size_t)NBLK * T_BYTES];
__device__ __align__(16) uint8_t g_Wprep[2 * T_BYTES];  // fp16 W1,W2 pre-swizzled

// smem: A double buffer + W1 + W2 + biases
#define SM_A0  0
#define SM_A1  (T_BYTES)
#define SM_W1  (2 * T_BYTES)
#define SM_W2  (3 * T_BYTES)
#define SM_B1  (4 * T_BYTES)
#define SM_B2  (4 * T_BYTES + 512)
#define SM_TOTAL (4 * T_BYTES + 1024)   // 140288

// ---------------------------------------------------------------------------
// helpers
// ---------------------------------------------------------------------------
__device__ __forceinline__ uint32_t smem_u32(const void* p) {
    uint32_t a;
    asm("{ .reg .u64 t; cvta.to.shared.u64 t, %1; cvt.u32.u64 %0, t; }"
        : "=r"(a) : "l"(p));
    return a;
}
#define CP_ASYNC16(saddr, gptr) \
    asm volatile("cp.async.cg.shared.global [%0], [%1], 16;" \
        :: "r"(saddr), "l"(gptr) : "memory")
#define CP_COMMIT() asm volatile("cp.async.commit_group;" ::: "memory")
#define CP_WAIT0()  asm volatile("cp.async.wait_group 0;" ::: "memory")

#define LDSM_X4(r0, r1, r2, r3, addr) \
    asm volatile("ldmatrix.sync.aligned.m8n8.x4.shared.b16 {%0,%1,%2,%3}, [%4];" \
        : "=r"(r0), "=r"(r1), "=r"(r2), "=r"(r3) : "r"(addr))

__device__ __forceinline__ void mma_f16(float* d, const uint32_t* a, const uint32_t* b) {
    asm volatile(
        "mma.sync.aligned.m16n8k16.row.col.f32.f16.f16.f32 "
        "{%0,%1,%2,%3}, {%4,%5,%6,%7}, {%8,%9}, {%0,%1,%2,%3};"
        : "+f"(d[0]), "+f"(d[1]), "+f"(d[2]), "+f"(d[3])
        : "r"(a[0]), "r"(a[1]), "r"(a[2]), "r"(a[3]), "r"(b[0]), "r"(b[1]));
}
__device__ __forceinline__ uint32_t packh2(float a, float b) {
    __half2 p = __floats2half2_rn(a, b);
    return *(uint32_t*)&p;
}

// ---------------------------------------------------------------------------
// Kernel A: zero counters + one-shot weight prep (fp16, [n][k], RB-stride)
// ---------------------------------------------------------------------------
__global__ void prep_kernel(const float* __restrict__ W1,
                            const float* __restrict__ W2) {
    int i = blockIdx.x * blockDim.x + threadIdx.x;
    if (i < N_NODES / 4) ((int4*)g_cnt)[i] = make_int4(0, 0, 0, 0);
    if (i == 0) g_ovf_cnt = 0;
    if (i < D * D) {
        int k = i >> 7, n = i & 127;
        uint32_t so = (uint32_t)(n * RB + (k >> 3) * 16 + (k & 7) * 2);
        *(__half*)(g_Wprep + so)           = __float2half_rn(W1[i]);
        *(__half*)(g_Wprep + T_BYTES + so) = __float2half_rn(W2[i]);
    }
}

// ---------------------------------------------------------------------------
// Kernel B: bucket edges by destination
// ---------------------------------------------------------------------------
__global__ void place_kernel(const int* __restrict__ ei) {
    int e = blockIdx.x * blockDim.x + threadIdx.x;
    if (e >= E_EDGES) return;
    int r = ei[e];              // source
    int c = ei[E_EDGES + e];    // destination
    int p = atomicAdd(&g_cnt[c], 1);
    if (p < CAP) {
        g_list[(size_t)c * CAP + p] = r;
    } else {
        int q = atomicAdd(&g_ovf_cnt, 1);
        if (q < OVF_MAX) g_ovf[q] = make_int2(r, c);
    }
}

// ---------------------------------------------------------------------------
// Kernel C: gather. One warp per node; lane owns 4 dims.
// Writes H = x + sum(x[src]) as fp16 directly in the swizzled MMA layout.
// Overflow (cnt > CAP) handled inline by the owning warp (scan of g_ovf).
// ---------------------------------------------------------------------------
__global__ void __launch_bounds__(256)
gather_kernel(const float* __restrict__ x) {
    int gw = (blockIdx.x * blockDim.x + threadIdx.x) >> 5;
    int lane = threadIdx.x & 31;
    if (gw >= N_NODES) return;
    int cnt0 = g_cnt[gw];
    int cnt = cnt0 > CAP ? CAP : cnt0;
    const float4* xr = (const float4*)x;
    float4 a0 = __ldg(&xr[(size_t)gw * 32 + lane]);
    float4 a1 = make_float4(0.f, 0.f, 0.f, 0.f);
    float4 a2 = make_float4(0.f, 0.f, 0.f, 0.f);
    float4 a3 = make_float4(0.f, 0.f, 0.f, 0.f);

    int mysrc = (lane < cnt) ? g_list[(size_t)gw * CAP + lane] : 0;
    int c2 = cnt < 32 ? cnt : 32;
    int i = 0;
    for (; i + 4 <= c2; i += 4) {
        int s0 = __shfl_sync(0xffffffffu, mysrc, i);
        int s1 = __shfl_sync(0xffffffffu, mysrc, i + 1);
        int s2 = __shfl_sync(0xffffffffu, mysrc, i + 2);
        int s3 = __shfl_sync(0xffffffffu, mysrc, i + 3);
        float4 v0 = __ldg(&xr[(size_t)s0 * 32 + lane]);
        float4 v1 = __ldg(&xr[(size_t)s1 * 32 + lane]);
        float4 v2 = __ldg(&xr[(size_t)s2 * 32 + lane]);
        float4 v3 = __ldg(&xr[(size_t)s3 * 32 + lane]);
        a0.x += v0.x; a0.y += v0.y; a0.z += v0.z; a0.w += v0.w;
        a1.x += v1.x; a1.y += v1.y; a1.z += v1.z; a1.w += v1.w;
        a2.x += v2.x; a2.y += v2.y; a2.z += v2.z; a2.w += v2.w;
        a3.x += v3.x; a3.y += v3.y; a3.z += v3.z; a3.w += v3.w;
    }
    for (; i < c2; i++) {
        int s = __shfl_sync(0xffffffffu, mysrc, i);
        float4 v = __ldg(&xr[(size_t)s * 32 + lane]);
        a0.x += v.x; a0.y += v.y; a0.z += v.z; a0.w += v.w;
    }
    for (int j = 32; j < cnt; j++) {                    // rare
        int s = g_list[(size_t)gw * CAP + j];
        float4 v = __ldg(&xr[(size_t)s * 32 + lane]);
        a0.x += v.x; a0.y += v.y; a0.z += v.z; a0.w += v.w;
    }
    if (cnt0 > CAP) {                                   // ultra-rare: scan ovf list
        int n = g_ovf_cnt; if (n > OVF_MAX) n = OVF_MAX;
        for (int e = 0; e < n; e++) {
            int2 ed = g_ovf[e];
            if (ed.y == gw) {
                float4 v = __ldg(&xr[(size_t)ed.x * 32 + lane]);
                a0.x += v.x; a0.y += v.y; a0.z += v.z; a0.w += v.w;
            }
        }
    }
    float4 acc;
    acc.x = (a0.x + a1.x) + (a2.x + a3.x);
    acc.y = (a0.y + a1.y) + (a2.y + a3.y);
    acc.z = (a0.z + a1.z) + (a2.z + a3.z);
    acc.w = (a0.w + a1.w) + (a2.w + a3.w);

    // store fp16 into swizzled MMA layout: tile = gw>>7, row = gw&127, col = 4*lane
    int t = gw >> 7, row = gw & 127;
    uint32_t so = (uint32_t)(row * RB + (lane >> 1) * 16 + (lane & 1) * 8);
    uint2 p;
    p.x = packh2(acc.x, acc.y);
    p.y = packh2(acc.z, acc.w);
    *(uint2*)(g_Hh + (size_t)t * T_BYTES + so) = p;
}

// ---------------------------------------------------------------------------
// Kernel D: persistent fp16 MLP, cp.async double-buffered A tiles.
// ---------------------------------------------------------------------------
__device__ __forceinline__ void warp_gemm(
    uint32_t sb, uint32_t a_t, uint32_t w_t,
    int m0, int n0, int lane, float acc[2][8][4])
{
    const int li = lane & 7;
    const int sub = lane >> 3;
    const uint32_t a_off = (uint32_t)((li + (sub & 1) * 8) * RB + (sub >> 1) * 16);
    const uint32_t b_off = (uint32_t)((li + (sub >> 1) * 8) * RB + (sub & 1) * 16);

    #pragma unroll
    for (int ks = 0; ks < 8; ks++) {
        const uint32_t kchunk = (uint32_t)(ks * 32);
        uint32_t ah[2][4];
        #pragma unroll
        for (int mi = 0; mi < 2; mi++) {
            uint32_t base = (uint32_t)((m0 + mi * 16) * RB) + a_off + kchunk;
            LDSM_X4(ah[mi][0], ah[mi][1], ah[mi][2], ah[mi][3], sb + a_t + base);
        }
        uint32_t bh[8][2];
        #pragma unroll
        for (int nj = 0; nj < 4; nj++) {
            uint32_t base = (uint32_t)((n0 + nj * 16) * RB) + b_off + kchunk;
            uint32_t r0, r1, r2, r3;
            LDSM_X4(r0, r1, r2, r3, sb + w_t + base);
            bh[nj * 2][0] = r0; bh[nj * 2][1] = r1;
            bh[nj * 2 + 1][0] = r2; bh[nj * 2 + 1][1] = r3;
        }
        #pragma unroll
        for (int mi = 0; mi < 2; mi++)
            #pragma unroll
            for (int ni = 0; ni < 8; ni++)
                mma_f16(acc[mi][ni], ah[mi], bh[ni]);
    }
}

__global__ void __launch_bounds__(256, 1)
mlp_mma_kernel(const float* __restrict__ b1, const float* __restrict__ b2,
               float* __restrict__ out) {
    extern __shared__ char smem[];
    const uint32_t sb = smem_u32(smem);
    const int tid = threadIdx.x;
    const int lane = tid & 31;
    const int wid = tid >> 5;
    const int m0 = (wid & 3) * 32;
    const int n0 = (wid >> 2) * 64;

    if (tid < 128) {
        ((float*)(smem + SM_B1))[tid] = b1[tid];
        ((float*)(smem + SM_B2))[tid] = b2[tid];
    }
    // stage W tiles once (persistent CTA) via cp.async
    {
        const char* wg = (const char*)g_Wprep;
        #pragma unroll 4
        for (int i = tid; i < 2 * T_BYTES / 16; i += 256)
            CP_ASYNC16(sb + SM_W1 + i * 16, wg + i * 16);
    }
    // prefetch first A tile into buf0
    {
        const char* hg = (const char*)(g_Hh + (size_t)blockIdx.x * T_BYTES);
        #pragma unroll 4
        for (int i = tid; i < T_BYTES / 16; i += 256)
            CP_ASYNC16(sb + SM_A0 + i * 16, hg + i * 16);
    }
    CP_COMMIT();

    int cur = 0;
    for (int t = blockIdx.x; t < NBLK; t += NSM) {
        CP_WAIT0();
        __syncthreads();                    // buf[cur] (and W on first iter) ready

        // prefetch next tile into the other buffer (overlaps with compute)
        int tn = t + NSM;
        if (tn < NBLK) {
            uint32_t dst = sb + (cur ? SM_A0 : SM_A1);
            const char* hg = (const char*)(g_Hh + (size_t)tn * T_BYTES);
            #pragma unroll 4
            for (int i = tid; i < T_BYTES / 16; i += 256)
                CP_ASYNC16(dst + i * 16, hg + i * 16);
        }
        CP_COMMIT();

        const uint32_t a_t = cur ? SM_A1 : SM_A0;
        float acc[2][8][4];

        // GEMM1: H1 = relu(A @ W1 + b1)
        #pragma unroll
        for (int mi = 0; mi < 2; mi++)
            #pragma unroll
            for (int ni = 0; ni < 8; ni++)
                #pragma unroll
                for (int q = 0; q < 4; q++) acc[mi][ni][q] = 0.0f;

        warp_gemm(sb, a_t, SM_W1, m0, n0, lane, acc);
        __syncthreads();

        {
            const float* b1s = (const float*)(smem + SM_B1);
            #pragma unroll
            for (int mi = 0; mi < 2; mi++) {
                int r0 = m0 + mi * 16 + (lane >> 2);
                #pragma unroll
                for (int ni = 0; ni < 8; ni++) {
                    int c0 = n0 + ni * 8 + (lane & 3) * 2;
                    float bb0 = b1s[c0], bb1 = b1s[c0 + 1];
                    float v00 = fmaxf(acc[mi][ni][0] + bb0, 0.0f);
                    float v01 = fmaxf(acc[mi][ni][1] + bb1, 0.0f);
                    float v10 = fmaxf(acc[mi][ni][2] + bb0, 0.0f);
                    float v11 = fmaxf(acc[mi][ni][3] + bb1, 0.0f);
                    uint32_t so0 = (uint32_t)(r0 * RB + (c0 >> 3) * 16 + (c0 & 7) * 2);
                    uint32_t so1 = so0 + 8 * RB;
                    *(uint32_t*)(smem + a_t + so0) = packh2(v00, v01);
                    *(uint32_t*)(smem + a_t + so1) = packh2(v10, v11);
                }
            }
        }
        __syncthreads();

        // GEMM2: out = H1 @ W2 + b2
        #pragma unroll
        for (int mi = 0; mi < 2; mi++)
            #pragma unroll
            for (int ni = 0; ni < 8; ni++)
                #pragma unroll
                for (int q = 0; q < 4; q++) acc[mi][ni][q] = 0.0f;

        warp_gemm(sb, a_t, SM_W2, m0, n0, lane, acc);

        {
            const float* b2s = (const float*)(smem + SM_B2);
            int base_m = t * MTILE + m0;
            #pragma unroll
            for (int mi = 0; mi < 2; mi++) {
                int gr0 = base_m + mi * 16 + (lane >> 2);
                int gr1 = gr0 + 8;
                #pragma unroll
                for (int ni = 0; ni < 8; ni++) {
                    int c0 = n0 + ni * 8 + (lane & 3) * 2;
                    float bb0 = b2s[c0], bb1 = b2s[c0 + 1];
                    if (gr0 < N_NODES) {
                        float2 v = make_float2(acc[mi][ni][0] + bb0, acc[mi][ni][1] + bb1);
                        *(float2*)(out + (size_t)gr0 * D + c0) = v;
                    }
                    if (gr1 < N_NODES) {
                        float2 v = make_float2(acc[mi][ni][2] + bb0, acc[mi][ni][3] + bb1);
                        *(float2*)(out + (size_t)gr1 * D + c0) = v;
                    }
                }
            }
        }
        __syncthreads();    // done with buf[cur] before next iter overwrites A region
        cur ^= 1;
    }
}

// ---------------------------------------------------------------------------
extern "C" void kernel_launch(void* const* d_in, const int* in_sizes, int n_in,
                              void* d_out, int out_size) {
    const float* x  = (const float*)d_in[0];
    const int*   ei = (const int*)d_in[1];
    const float* W1 = (const float*)d_in[2];
    const float* b1 = (const float*)d_in[3];
    const float* W2 = (const float*)d_in[4];
    const float* b2 = (const float*)d_in[5];
    float*       out = (float*)d_out;

    prep_kernel<<<(N_NODES / 4 + 255) / 256, 256>>>(W1, W2);
    place_kernel<<<(E_EDGES + 255) / 256, 256>>>(ei);
    gather_kernel<<<(N_NODES * 32 + 255) / 256, 256>>>(x);
    {
        cudaFuncSetAttribute(mlp_mma_kernel,
                             cudaFuncAttributeMaxDynamicSharedMemorySize, SM_TOTAL);
        mlp_mma_kernel<<<NSM, 256, SM_TOTAL>>>(b1, b2, out);
    }
}

// round 9
// speedup vs baseline: 3.4872x; 1.0611x over previous
#include <cuda_runtime.h>
#include <cuda_fp16.h>
#include <cstdint>

#define N_NODES 100000
#define D 128
#define E_EDGES 640000

#define MTILE 128
#define NBLK 782                 // 782 * 128 = 100096
#define NSM 148

#define CAP 40                   // in-degree capacity (Poisson(6.4): P(>40)~1e-12)
#define OVF_MAX 4096

// ---- MMA smem tile layout (row stride 272B keeps ldmatrix conflict-free) ----
#define RB 272
#define T_BYTES (128 * RB)          // 34816 per tile

__device__ int   g_cnt[N_NODES];
__device__ int   g_list[(size_t)N_NODES * CAP];
__device__ int   g_ovf_cnt;
__device__ int2  g_ovf[OVF_MAX];
__device__ __align__(16) __half g_xh[(size_t)N_NODES * D];     // fp16 copy of x
// H in fp16, pre-swizzled MMA layout, one T_BYTES block per 128-row tile
__device__ __align__(16) uint8_t g_Hh[(size_t)NBLK * T_BYTES];
__device__ __align__(16) uint8_t g_Wprep[2 * T_BYTES];  // fp16 W1,W2 pre-swizzled

// smem: A double buffer + W1 + W2 + biases
#define SM_A0  0
#define SM_A1  (T_BYTES)
#define SM_W1  (2 * T_BYTES)
#define SM_W2  (3 * T_BYTES)
#define SM_B1  (4 * T_BYTES)
#define SM_B2  (4 * T_BYTES + 512)
#define SM_TOTAL (4 * T_BYTES + 1024)   // 140288

#define MLP_T 512                       // 16 warps, warp tile 32x32

// ---------------------------------------------------------------------------
// helpers
// ---------------------------------------------------------------------------
__device__ __forceinline__ uint32_t smem_u32(const void* p) {
    uint32_t a;
    asm("{ .reg .u64 t; cvta.to.shared.u64 t, %1; cvt.u32.u64 %0, t; }"
        : "=r"(a) : "l"(p));
    return a;
}
#define CP_ASYNC16(saddr, gptr) \
    asm volatile("cp.async.cg.shared.global [%0], [%1], 16;" \
        :: "r"(saddr), "l"(gptr) : "memory")
#define CP_COMMIT() asm volatile("cp.async.commit_group;" ::: "memory")
#define CP_WAIT0()  asm volatile("cp.async.wait_group 0;" ::: "memory")

#define LDSM_X4(r0, r1, r2, r3, addr) \
    asm volatile("ldmatrix.sync.aligned.m8n8.x4.shared.b16 {%0,%1,%2,%3}, [%4];" \
        : "=r"(r0), "=r"(r1), "=r"(r2), "=r"(r3) : "r"(addr))

__device__ __forceinline__ void mma_f16(float* d, const uint32_t* a, const uint32_t* b) {
    asm volatile(
        "mma.sync.aligned.m16n8k16.row.col.f32.f16.f16.f32 "
        "{%0,%1,%2,%3}, {%4,%5,%6,%7}, {%8,%9}, {%0,%1,%2,%3};"
        : "+f"(d[0]), "+f"(d[1]), "+f"(d[2]), "+f"(d[3])
        : "r"(a[0]), "r"(a[1]), "r"(a[2]), "r"(a[3]), "r"(b[0]), "r"(b[1]));
}
__device__ __forceinline__ uint32_t packh2(float a, float b) {
    __half2 p = __floats2half2_rn(a, b);
    return *(uint32_t*)&p;
}
__device__ __forceinline__ void addh2(float& a, float& b, uint32_t p) {
    float2 f = __half22float2(*(__half2*)&p);
    a += f.x; b += f.y;
}

// ---------------------------------------------------------------------------
// Kernel A: zero counters + W prep + x -> fp16 conversion
// ---------------------------------------------------------------------------
__global__ void prep_kernel(const float* __restrict__ x,
                            const float* __restrict__ W1,
                            const float* __restrict__ W2) {
    int i = blockIdx.x * blockDim.x + threadIdx.x;
    if (i < N_NODES * 32) {                // x: one float4 -> uint2 (4 halves)
        float4 v = ((const float4*)x)[i];
        uint2 p;
        p.x = packh2(v.x, v.y);
        p.y = packh2(v.z, v.w);
        ((uint2*)g_xh)[i] = p;
    }
    if (i < N_NODES / 4) ((int4*)g_cnt)[i] = make_int4(0, 0, 0, 0);
    if (i == 0) g_ovf_cnt = 0;
    if (i < D * D) {
        int k = i >> 7, n = i & 127;
        uint32_t so = (uint32_t)(n * RB + (k >> 3) * 16 + (k & 7) * 2);
        *(__half*)(g_Wprep + so)           = __float2half_rn(W1[i]);
        *(__half*)(g_Wprep + T_BYTES + so) = __float2half_rn(W2[i]);
    }
}

// ---------------------------------------------------------------------------
// Kernel B: bucket edges by destination (2 edges per thread)
// ---------------------------------------------------------------------------
__global__ void place_kernel(const int* __restrict__ ei) {
    int t = blockIdx.x * blockDim.x + threadIdx.x;
    #pragma unroll
    for (int u = 0; u < 2; u++) {
        int e = t * 2 + u;
        if (e >= E_EDGES) return;
        int r = ei[e];              // source
        int c = ei[E_EDGES + e];    // destination
        int p = atomicAdd(&g_cnt[c], 1);
        if (p < CAP) {
            g_list[(size_t)c * CAP + p] = r;
        } else {
            int q = atomicAdd(&g_ovf_cnt, 1);
            if (q < OVF_MAX) g_ovf[q] = make_int2(r, c);
        }
    }
}

// ---------------------------------------------------------------------------
// Kernel C: gather from fp16 x. One warp per node; lane owns 4 dims (8B).
// fp32 accumulation; writes fp16 H in swizzled MMA layout.
// ---------------------------------------------------------------------------
__global__ void __launch_bounds__(256)
gather_kernel() {
    int gw = (blockIdx.x * blockDim.x + threadIdx.x) >> 5;
    int lane = threadIdx.x & 31;
    if (gw >= N_NODES) return;
    int cnt0 = g_cnt[gw];
    int cnt = cnt0 > CAP ? CAP : cnt0;
    const uint2* xr = (const uint2*)g_xh;    // 32 uint2 per row

    uint2 own = __ldg(&xr[(size_t)gw * 32 + lane]);
    float ax0 = 0.f, ay0 = 0.f, az0 = 0.f, aw0 = 0.f;
    float ax1 = 0.f, ay1 = 0.f, az1 = 0.f, aw1 = 0.f;
    float ax2 = 0.f, ay2 = 0.f, az2 = 0.f, aw2 = 0.f;
    float ax3 = 0.f, ay3 = 0.f, az3 = 0.f, aw3 = 0.f;
    addh2(ax0, ay0, own.x); addh2(az0, aw0, own.y);

    int mysrc = (lane < cnt) ? g_list[(size_t)gw * CAP + lane] : 0;
    int c2 = cnt < 32 ? cnt : 32;
    int i = 0;
    for (; i + 4 <= c2; i += 4) {
        int s0 = __shfl_sync(0xffffffffu, mysrc, i);
        int s1 = __shfl_sync(0xffffffffu, mysrc, i + 1);
        int s2 = __shfl_sync(0xffffffffu, mysrc, i + 2);
        int s3 = __shfl_sync(0xffffffffu, mysrc, i + 3);
        uint2 v0 = __ldg(&xr[(size_t)s0 * 32 + lane]);
        uint2 v1 = __ldg(&xr[(size_t)s1 * 32 + lane]);
        uint2 v2 = __ldg(&xr[(size_t)s2 * 32 + lane]);
        uint2 v3 = __ldg(&xr[(size_t)s3 * 32 + lane]);
        addh2(ax0, ay0, v0.x); addh2(az0, aw0, v0.y);
        addh2(ax1, ay1, v1.x); addh2(az1, aw1, v1.y);
        addh2(ax2, ay2, v2.x); addh2(az2, aw2, v2.y);
        addh2(ax3, ay3, v3.x); addh2(az3, aw3, v3.y);
    }
    for (; i < c2; i++) {
        int s = __shfl_sync(0xffffffffu, mysrc, i);
        uint2 v = __ldg(&xr[(size_t)s * 32 + lane]);
        addh2(ax0, ay0, v.x); addh2(az0, aw0, v.y);
    }
    for (int j = 32; j < cnt; j++) {                    // rare
        int s = g_list[(size_t)gw * CAP + j];
        uint2 v = __ldg(&xr[(size_t)s * 32 + lane]);
        addh2(ax0, ay0, v.x); addh2(az0, aw0, v.y);
    }
    if (cnt0 > CAP) {                                   // ultra-rare: scan ovf list
        int n = g_ovf_cnt; if (n > OVF_MAX) n = OVF_MAX;
        for (int e = 0; e < n; e++) {
            int2 ed = g_ovf[e];
            if (ed.y == gw) {
                uint2 v = __ldg(&xr[(size_t)ed.x * 32 + lane]);
                addh2(ax0, ay0, v.x); addh2(az0, aw0, v.y);
            }
        }
    }
    float fx = (ax0 + ax1) + (ax2 + ax3);
    float fy = (ay0 + ay1) + (ay2 + ay3);
    float fz = (az0 + az1) + (az2 + az3);
    float fw = (aw0 + aw1) + (aw2 + aw3);

    // store fp16 into swizzled MMA layout: tile = gw>>7, row = gw&127, col = 4*lane
    int t = gw >> 7, row = gw & 127;
    uint32_t so = (uint32_t)(row * RB + (lane >> 1) * 16 + (lane & 1) * 8);
    uint2 p;
    p.x = packh2(fx, fy);
    p.y = packh2(fz, fw);
    *(uint2*)(g_Hh + (size_t)t * T_BYTES + so) = p;
}

// ---------------------------------------------------------------------------
// Kernel D: persistent fp16 MLP, 512 threads (16 warps, 32x32 warp tiles),
// cp.async double-buffered A tiles.
// ---------------------------------------------------------------------------
__device__ __forceinline__ void warp_gemm(
    uint32_t sb, uint32_t a_t, uint32_t w_t,
    int m0, int n0, int lane, float acc[2][4][4])
{
    const int li = lane & 7;
    const int sub = lane >> 3;
    const uint32_t a_off = (uint32_t)((li + (sub & 1) * 8) * RB + (sub >> 1) * 16);
    const uint32_t b_off = (uint32_t)((li + (sub >> 1) * 8) * RB + (sub & 1) * 16);

    #pragma unroll
    for (int ks = 0; ks < 8; ks++) {
        const uint32_t kchunk = (uint32_t)(ks * 32);
        uint32_t ah[2][4];
        #pragma unroll
        for (int mi = 0; mi < 2; mi++) {
            uint32_t base = (uint32_t)((m0 + mi * 16) * RB) + a_off + kchunk;
            LDSM_X4(ah[mi][0], ah[mi][1], ah[mi][2], ah[mi][3], sb + a_t + base);
        }
        uint32_t bh[4][2];
        #pragma unroll
        for (int nj = 0; nj < 2; nj++) {
            uint32_t base = (uint32_t)((n0 + nj * 16) * RB) + b_off + kchunk;
            uint32_t r0, r1, r2, r3;
            LDSM_X4(r0, r1, r2, r3, sb + w_t + base);
            bh[nj * 2][0] = r0; bh[nj * 2][1] = r1;
            bh[nj * 2 + 1][0] = r2; bh[nj * 2 + 1][1] = r3;
        }
        #pragma unroll
        for (int mi = 0; mi < 2; mi++)
            #pragma unroll
            for (int ni = 0; ni < 4; ni++)
                mma_f16(acc[mi][ni], ah[mi], bh[ni]);
    }
}

__global__ void __launch_bounds__(MLP_T, 1)
mlp_mma_kernel(const float* __restrict__ b1, const float* __restrict__ b2,
               float* __restrict__ out) {
    extern __shared__ char smem[];
    const uint32_t sb = smem_u32(smem);
    const int tid = threadIdx.x;
    const int lane = tid & 31;
    const int wid = tid >> 5;
    const int m0 = (wid & 3) * 32;     // 4 m-tiles
    const int n0 = (wid >> 2) * 32;    // 4 n-tiles

    if (tid < 128) {
        ((float*)(smem + SM_B1))[tid] = b1[tid];
        ((float*)(smem + SM_B2))[tid] = b2[tid];
    }
    // stage W tiles once via cp.async
    {
        const char* wg = (const char*)g_Wprep;
        #pragma unroll 4
        for (int i = tid; i < 2 * T_BYTES / 16; i += MLP_T)
            CP_ASYNC16(sb + SM_W1 + i * 16, wg + i * 16);
    }
    // prefetch first A tile into buf0
    {
        const char* hg = (const char*)(g_Hh + (size_t)blockIdx.x * T_BYTES);
        #pragma unroll 4
        for (int i = tid; i < T_BYTES / 16; i += MLP_T)
            CP_ASYNC16(sb + SM_A0 + i * 16, hg + i * 16);
    }
    CP_COMMIT();

    int cur = 0;
    for (int t = blockIdx.x; t < NBLK; t += NSM) {
        CP_WAIT0();
        __syncthreads();                    // buf[cur] (and W on first iter) ready

        // prefetch next tile into the other buffer (overlaps with compute)
        int tn = t + NSM;
        if (tn < NBLK) {
            uint32_t dst = sb + (cur ? SM_A0 : SM_A1);
            const char* hg = (const char*)(g_Hh + (size_t)tn * T_BYTES);
            #pragma unroll 4
            for (int i = tid; i < T_BYTES / 16; i += MLP_T)
                CP_ASYNC16(dst + i * 16, hg + i * 16);
        }
        CP_COMMIT();

        const uint32_t a_t = cur ? SM_A1 : SM_A0;
        float acc[2][4][4];

        // GEMM1: H1 = relu(A @ W1 + b1)
        #pragma unroll
        for (int mi = 0; mi < 2; mi++)
            #pragma unroll
            for (int ni = 0; ni < 4; ni++)
                #pragma unroll
                for (int q = 0; q < 4; q++) acc[mi][ni][q] = 0.0f;

        warp_gemm(sb, a_t, SM_W1, m0, n0, lane, acc);
        __syncthreads();

        {
            const float* b1s = (const float*)(smem + SM_B1);
            #pragma unroll
            for (int mi = 0; mi < 2; mi++) {
                int r0 = m0 + mi * 16 + (lane >> 2);
                #pragma unroll
                for (int ni = 0; ni < 4; ni++) {
                    int c0 = n0 + ni * 8 + (lane & 3) * 2;
                    float bb0 = b1s[c0], bb1 = b1s[c0 + 1];
                    float v00 = fmaxf(acc[mi][ni][0] + bb0, 0.0f);
                    float v01 = fmaxf(acc[mi][ni][1] + bb1, 0.0f);
                    float v10 = fmaxf(acc[mi][ni][2] + bb0, 0.0f);
                    float v11 = fmaxf(acc[mi][ni][3] + bb1, 0.0f);
                    uint32_t so0 = (uint32_t)(r0 * RB + (c0 >> 3) * 16 + (c0 & 7) * 2);
                    uint32_t so1 = so0 + 8 * RB;
                    *(uint32_t*)(smem + a_t + so0) = packh2(v00, v01);
                    *(uint32_t*)(smem + a_t + so1) = packh2(v10, v11);
                }
            }
        }
        __syncthreads();

        // GEMM2: out = H1 @ W2 + b2
        #pragma unroll
        for (int mi = 0; mi < 2; mi++)
            #pragma unroll
            for (int ni = 0; ni < 4; ni++)
                #pragma unroll
                for (int q = 0; q < 4; q++) acc[mi][ni][q] = 0.0f;

        warp_gemm(sb, a_t, SM_W2, m0, n0, lane, acc);

        {
            const float* b2s = (const float*)(smem + SM_B2);
            int base_m = t * MTILE + m0;
            #pragma unroll
            for (int mi = 0; mi < 2; mi++) {
                int gr0 = base_m + mi * 16 + (lane >> 2);
                int gr1 = gr0 + 8;
                #pragma unroll
                for (int ni = 0; ni < 4; ni++) {
                    int c0 = n0 + ni * 8 + (lane & 3) * 2;
                    float bb0 = b2s[c0], bb1 = b2s[c0 + 1];
                    if (gr0 < N_NODES) {
                        float2 v = make_float2(acc[mi][ni][0] + bb0, acc[mi][ni][1] + bb1);
                        *(float2*)(out + (size_t)gr0 * D + c0) = v;
                    }
                    if (gr1 < N_NODES) {
                        float2 v = make_float2(acc[mi][ni][2] + bb0, acc[mi][ni][3] + bb1);
                        *(float2*)(out + (size_t)gr1 * D + c0) = v;
                    }
                }
            }
        }
        __syncthreads();    // done with buf[cur] before next iter overwrites A region
        cur ^= 1;
    }
}

// ---------------------------------------------------------------------------
extern "C" void kernel_launch(void* const* d_in, const int* in_sizes, int n_in,
                              void* d_out, int out_size) {
    const float* x  = (const float*)d_in[0];
    const int*   ei = (const int*)d_in[1];
    const float* W1 = (const float*)d_in[2];
    const float* b1 = (const float*)d_in[3];
    const float* W2 = (const float*)d_in[4];
    const float* b2 = (const float*)d_in[5];
    float*       out = (float*)d_out;

    prep_kernel<<<(N_NODES * 32 + 255) / 256, 256>>>(x, W1, W2);
    place_kernel<<<(E_EDGES / 2 + 255) / 256, 256>>>(ei);
    gather_kernel<<<(N_NODES * 32 + 255) / 256, 256>>>();
    {
        cudaFuncSetAttribute(mlp_mma_kernel,
                             cudaFuncAttributeMaxDynamicSharedMemorySize, SM_TOTAL);
        mlp_mma_kernel<<<NSM, MLP_T, SM_TOTAL>>>(b1, b2, out);
    }
}